// round 8
// baseline (speedup 1.0000x reference)
#include <cuda_runtime.h>
#include <math.h>

#define TINYF 1.17549435e-38f

// ---------------- precomputed HMM parameters (device globals) ----------------
__device__ __align__(16) float g_em[25 * 512];   // transposed match emissions [sym][m]
__device__ float g_insd[32];                     // insert/flank emission dist
__device__ __align__(16) float g_enter[512];
__device__ __align__(16) float g_mtm[512];       // mtm_p[m-1]
__device__ __align__(16) float g_i2m[512];       // i2m_p[m-1]
__device__ __align__(16) float g_dtm[512];       // dtm_p[m-1]
__device__ __align__(16) float g_m2e[512];       // m2e_tot[m]
__device__ __align__(16) float g_m2i[512];       // m2i_p[m]
__device__ __align__(16) float g_i2i[512];       // i2i_p[m]
__device__ __align__(16) float g_asc[512];       // scan mult dtd_p[m-1] (a_0 = 1)
__device__ __align__(16) float g_msc[512];       // scan coeff mtd_p[m]
__device__ float g_scal[8];                      // floop,fexit,be,ep0,ep1,p0

// ---------------- setup: build all derived parameters (1 block, 512 thr) ----
__global__ void setup_kernel(
    const float* __restrict__ em_kernel, const float* __restrict__ ins_kernel,
    const float* __restrict__ flank_kernel, const float* __restrict__ btm,
    const float* __restrict__ m2e, const float* __restrict__ mtm,
    const float* __restrict__ m2i, const float* __restrict__ i2m,
    const float* __restrict__ i2i, const float* __restrict__ mtd,
    const float* __restrict__ dtm, const float* __restrict__ dtd,
    const float* __restrict__ lf_loop, const float* __restrict__ lf_exit,
    const float* __restrict__ e2u, const float* __restrict__ e2r,
    const float* __restrict__ e2t)
{
    __shared__ float red[512];
    __shared__ float incl[512];
    int m = threadIdx.x;

    float dtmp_m1 = 0.f, dtdp_m1 = 0.f;
    if (m >= 1) {
        float a = dtm[m-1], b = dtd[m-1], mx = fmaxf(a, b);
        float ea = expf(a-mx), eb = expf(b-mx), z = ea+eb;
        dtmp_m1 = ea/z; dtdp_m1 = eb/z;
    }
    float dtdp_m = 0.f;
    if (m <= 510) {
        float a = dtm[m], b = dtd[m], mx = fmaxf(a, b);
        float ea = expf(a-mx), eb = expf(b-mx);
        dtdp_m = eb/(ea+eb);
    }
    float m2ip_m = 0.f, m2ep_m = 0.f, mtdp_next = 0.f;
    if (m <= 510) {
        float v0 = mtm[m], v1 = m2i[m], v2 = m2e[m], v3 = mtd[m+1];
        float mx = fmaxf(fmaxf(v0,v1), fmaxf(v2,v3));
        float e0 = expf(v0-mx), e1 = expf(v1-mx), e2 = expf(v2-mx), e3 = expf(v3-mx);
        float z = e0+e1+e2+e3;
        m2ip_m = e1/z; m2ep_m = e2/z; mtdp_next = e3/z;
    }
    float mtmp_m1 = 0.f, mtdp_m_mid = 0.f;
    if (m >= 1) {
        float v0 = mtm[m-1], v1 = m2i[m-1], v2 = m2e[m-1], v3 = mtd[m];
        float mx = fmaxf(fmaxf(v0,v1), fmaxf(v2,v3));
        float e0 = expf(v0-mx), e1 = expf(v1-mx), e2 = expf(v2-mx), e3 = expf(v3-mx);
        float z = e0+e1+e2+e3;
        mtmp_m1 = e0/z; mtdp_m_mid = e3/z;
    }
    float i2ip_m = 0.f;
    if (m <= 510) {
        float a = i2m[m], b = i2i[m], mx = fmaxf(a, b);
        float ea = expf(a-mx), eb = expf(b-mx);
        i2ip_m = eb/(ea+eb);
    }
    float i2mp_m1 = 0.f;
    if (m >= 1) {
        float a = i2m[m-1], b = i2i[m-1], mx = fmaxf(a, b);
        float ea = expf(a-mx), eb = expf(b-mx);
        i2mp_m1 = ea/(ea+eb);
    }

    // begin softmax over [btm(512), mtd[0]]
    float bx = btm[m];
    red[m] = bx; __syncthreads();
    for (int s = 256; s > 0; s >>= 1) { if (m < s) red[m] = fmaxf(red[m], red[m+s]); __syncthreads(); }
    float bmx = fmaxf(red[0], mtd[0]);
    __syncthreads();
    float bex = expf(bx - bmx);
    red[m] = bex; __syncthreads();
    for (int s = 256; s > 0; s >>= 1) { if (m < s) red[m] += red[m+s]; __syncthreads(); }
    float bz = red[0] + expf(mtd[0] - bmx);
    __syncthreads();
    float btmp_m  = bex / bz;
    float mtd_p0  = expf(mtd[0] - bmx) / bz;

    // cp prefix sum
    incl[m] = (m <= 510) ? logf(dtdp_m) : 0.f;
    __syncthreads();
    for (int d = 1; d < 512; d <<= 1) {
        float v = incl[m];
        float add = (m >= d) ? incl[m-d] : 0.f;
        __syncthreads();
        incl[m] = v + add;
        __syncthreads();
    }
    float cp511 = incl[510];
    float cpm1  = (m >= 2) ? incl[m-2] : 0.f;
    float cpp1  = incl[m];
    float be = mtd_p0 * expf(cp511);
    float enter_m = btmp_m + ((m >= 1) ? mtd_p0 * expf(cpm1) * dtmp_m1 : 0.f);
    float m2etot = (m <= 510) ? (m2ep_m + mtdp_next * expf(cp511 - cpp1)) : 1.f;
    float mtdp_m = (m == 0) ? mtd_p0 : mtdp_m_mid;

    g_enter[m] = enter_m;
    g_mtm[m]   = mtmp_m1;
    g_i2m[m]   = i2mp_m1;
    g_dtm[m]   = (m >= 1) ? dtmp_m1 : 0.f;
    g_m2e[m]   = m2etot;
    g_m2i[m]   = m2ip_m;
    g_i2i[m]   = i2ip_m;
    g_asc[m]   = (m >= 1) ? dtdp_m1 : 1.f;
    g_msc[m]   = mtdp_m;

    {
        const float* row = em_kernel + m * 25;
        float mxr = row[0];
        for (int s = 1; s < 25; s++) mxr = fmaxf(mxr, row[s]);
        float z = 0.f;
        for (int s = 0; s < 25; s++) z += expf(row[s] - mxr);
        float invz = 1.f / z;
        for (int s = 0; s < 25; s++) g_em[s * 512 + m] = expf(row[s] - mxr) * invz;
    }
    if (m == 0) {
        float mxi = ins_kernel[0];
        for (int s = 1; s < 25; s++) mxi = fmaxf(mxi, ins_kernel[s]);
        float z = 0.f;
        for (int s = 0; s < 25; s++) z += expf(ins_kernel[s] - mxi);
        for (int s = 0; s < 25; s++) g_insd[s] = expf(ins_kernel[s] - mxi) / z;
        float a = lf_loop[0], b = lf_exit[0], mx = fmaxf(a, b);
        float ea = expf(a-mx), eb = expf(b-mx), z2 = ea+eb;
        float u = e2u[0], r = e2r[0], t = e2t[0];
        float mxe = fmaxf(fmaxf(u, r), t);
        float eu = expf(u-mxe), er = expf(r-mxe), et = expf(t-mxe);
        float ze = eu + er + et;
        g_scal[0] = ea/z2;  // floop
        g_scal[1] = eb/z2;  // fexit
        g_scal[2] = be;
        g_scal[3] = eu/ze;  // ep0
        g_scal[4] = er/ze;  // ep1
        g_scal[5] = 1.f / (1.f + expf(-flank_kernel[0]));  // p0
    }
}

// ---------------- forward kernel: 1 CTA = 1 warp per batch, 16 states/lane --
__global__ __launch_bounds__(32, 1)
void fwd_kernel(const int* __restrict__ seq, float* __restrict__ out)
{
    __shared__ int   s_seq[1024];
    __shared__ float s_insd[32];
    __shared__ __align__(16) float s_mec[512];
    __shared__ __align__(16) float s_mic[512];
    __shared__ __align__(16) float s_iic[512];

    const int lane = threadIdx.x;
    const int b = blockIdx.x;
    const int m0 = lane * 16;
    const unsigned FULL = 0xffffffffu;

    // stage sequence + insert dist + cold constant arrays
    {
        const int4* sp = (const int4*)(seq + b * 1024);
        #pragma unroll
        for (int k = 0; k < 8; k++)
            ((int4*)s_seq)[lane + 32 * k] = sp[lane + 32 * k];
        if (lane < 25) s_insd[lane] = g_insd[lane];
        #pragma unroll
        for (int k = 0; k < 4; k++) {
            ((float4*)s_mec)[lane + 32 * k] = ((const float4*)g_m2e)[lane + 32 * k];
            ((float4*)s_mic)[lane + 32 * k] = ((const float4*)g_m2i)[lane + 32 * k];
            ((float4*)s_iic)[lane + 32 * k] = ((const float4*)g_i2i)[lane + 32 * k];
        }
    }

    // per-thread hot constants (16 states each)
    float en[16], mtc[16], i2mc[16], asc[16], msc[16], dtc[16];
    #pragma unroll
    for (int h = 0; h < 4; h++) {
        int o = m0 + 4 * h;
        float4 v;
        v = *(const float4*)(g_enter + o); en[4*h]=v.x; en[4*h+1]=v.y; en[4*h+2]=v.z; en[4*h+3]=v.w;
        v = *(const float4*)(g_mtm   + o); mtc[4*h]=v.x; mtc[4*h+1]=v.y; mtc[4*h+2]=v.z; mtc[4*h+3]=v.w;
        v = *(const float4*)(g_i2m   + o); i2mc[4*h]=v.x; i2mc[4*h+1]=v.y; i2mc[4*h+2]=v.z; i2mc[4*h+3]=v.w;
        v = *(const float4*)(g_dtm   + o); dtc[4*h]=v.x; dtc[4*h+1]=v.y; dtc[4*h+2]=v.z; dtc[4*h+3]=v.w;
        v = *(const float4*)(g_asc   + o); asc[4*h]=v.x; asc[4*h+1]=v.y; asc[4*h+2]=v.z; asc[4*h+3]=v.w;
        v = *(const float4*)(g_msc   + o); msc[4*h]=v.x; msc[4*h+1]=v.y; msc[4*h+2]=v.z; msc[4*h+3]=v.w;
    }
    // scaled-prefix constants
    float P[16];
    P[0] = asc[0];
    #pragma unroll
    for (int k = 1; k < 16; k++) P[k] = P[k-1] * asc[k];
    float mscP[16], dtcP[16];
    #pragma unroll
    for (int k = 0; k < 16; k++) mscP[k] = msc[k] / P[k];
    dtcP[0] = dtc[0];
    #pragma unroll
    for (int k = 1; k < 16; k++) dtcP[k] = dtc[k] * P[k-1];
    const float segA = P[15];
    const float cU   = P[15];
    const float mscP0 = mscP[0];

    const float floop = g_scal[0], fexit = g_scal[1], be = g_scal[2];
    const float ep0 = g_scal[3], ep1 = g_scal[4], p0 = g_scal[5];
    const float fbe0 = fexit * be * ep0, fbe1 = fexit * be * ep1;

    // prolog: radix-4 scan constants on the SHIFTED per-lane A (As_j = segA_{j-1})
    float c11, c12, c13, c21, c22, c23, c31;
    {
        float As = __shfl_up_sync(FULL, segA, 1);
        if (lane == 0) As = 1.f;
        float a1 = __shfl_up_sync(FULL, As, 1);
        float a2 = __shfl_up_sync(FULL, As, 2);
        float a3 = __shfl_up_sync(FULL, As, 3);
        c11 = (lane >= 1) ? As : 0.f;
        c12 = (lane >= 2) ? As * a1 : 0.f;
        c13 = (lane >= 3) ? As * a1 * a2 : 0.f;
        float G1 = As;
        if (lane >= 1) G1 *= a1;
        if (lane >= 2) G1 *= a2;
        if (lane >= 3) G1 *= a3;
        float g1 = __shfl_up_sync(FULL, G1, 4);
        float g2 = __shfl_up_sync(FULL, G1, 8);
        float g3 = __shfl_up_sync(FULL, G1, 12);
        c21 = (lane >= 4)  ? G1 : 0.f;
        c22 = (lane >= 8)  ? G1 * g1 : 0.f;
        c23 = (lane >= 12) ? G1 * g1 * g2 : 0.f;
        float G2 = G1;
        if (lane >= 4)  G2 *= g1;
        if (lane >= 8)  G2 *= g2;
        if (lane >= 12) G2 *= g3;
        c31 = (lane >= 16) ? G2 : 0.f;
    }
    __syncwarp();

    // ---- t = 0 init ----
    int c = s_seq[0];
    float eins = s_insd[c];
    float aM[16], aI[16], em[16], pre[16];
    #pragma unroll
    for (int h = 0; h < 4; h++) {
        float4 ev = __ldg((const float4*)(g_em + c * 512 + m0 + 4*h));
        em[4*h]=ev.x; em[4*h+1]=ev.y; em[4*h+2]=ev.z; em[4*h+3]=ev.w;
    }
    const float q0 = 1.f - p0;
    #pragma unroll
    for (int k = 0; k < 16; k++) { aM[k] = q0 * en[k] * em[k]; aI[k] = 0.f; }
    float aLF = p0 * eins, aU = q0 * be * ep0 * eins, aRF = q0 * be * ep1 * eins;
    float ll;
    {
        float tp = 0.f;
        #pragma unroll
        for (int k = 0; k < 16; k++) tp += aM[k];
        #pragma unroll
        for (int d = 16; d; d >>= 1) tp += __shfl_xor_sync(FULL, tp, d);
        float s = tp + aLF + aU + aRF + TINYF;
        float inv = 1.f / s; ll = logf(s);
        #pragma unroll
        for (int k = 0; k < 16; k++) aM[k] *= inv;
        aLF *= inv; aU *= inv; aRF *= inv;
    }

    // ---- main recurrence: no block barrier; rescale every 16 steps ----
    for (int t = 1; t < 1024; t++) {
        const bool rescale = ((t & 15) == 0);

        c = s_seq[t];
        eins = s_insd[c];
        #pragma unroll
        for (int h = 0; h < 4; h++) {
            float4 ev = __ldg((const float4*)(g_em + c * 512 + m0 + 4*h));
            em[4*h]=ev.x; em[4*h+1]=ev.y; em[4*h+2]=ev.z; em[4*h+3]=ev.w;
        }

        float prevM = __shfl_up_sync(FULL, aM[15], 1);
        float prevI = __shfl_up_sync(FULL, aI[15], 1);
        if (lane == 0) { prevM = 0.f; prevI = 0.f; }

        const float fc = fexit * (aLF + aU);

        // pre[k] + running scaled sum u2 (seeded with boundary term)
        pre[0] = fmaf(i2mc[0], prevI, fmaf(mtc[0], prevM, en[0]*fc));
        float u2 = mscP0 * prevM;
        #pragma unroll
        for (int k = 1; k < 16; k++) {
            pre[k] = fmaf(dtcP[k], u2,
                     fmaf(i2mc[k], aI[k-1],
                     fmaf(mtc[k], aM[k-1], en[k]*fc)));
            u2 = fmaf(aM[k-1], mscP[k], u2);
        }
        float iB = cU * u2;

        // mexit dot (smem coeffs) + butterfly (off critical path)
        float mx = 0.f;
        #pragma unroll
        for (int h = 0; h < 4; h++) {
            float4 me = *(const float4*)(s_mec + m0 + 4*h);
            mx = fmaf(me.x, aM[4*h],   mx);
            mx = fmaf(me.y, aM[4*h+1], mx);
            mx = fmaf(me.z, aM[4*h+2], mx);
            mx = fmaf(me.w, aM[4*h+3], mx);
        }
        #pragma unroll
        for (int d = 16; d; d >>= 1) mx += __shfl_xor_sync(FULL, mx, d);

        float tp = 0.f;
        if (rescale) {
            #pragma unroll
            for (int k = 0; k < 16; k++) tp += aM[k] + aI[k];
            #pragma unroll
            for (int d = 16; d; d >>= 1) tp += __shfl_xor_sync(FULL, tp, d);
        }

        // insert states: write in place (reads only old aM/aI)
        #pragma unroll
        for (int h = 0; h < 4; h++) {
            float4 mi = *(const float4*)(s_mic + m0 + 4*h);
            float4 ii = *(const float4*)(s_iic + m0 + 4*h);
            aI[4*h]   = eins * fmaf(mi.x, aM[4*h],   ii.x * aI[4*h]);
            aI[4*h+1] = eins * fmaf(mi.y, aM[4*h+1], ii.y * aI[4*h+1]);
            aI[4*h+2] = eins * fmaf(mi.z, aM[4*h+2], ii.z * aI[4*h+2]);
            aI[4*h+3] = eins * fmaf(mi.w, aM[4*h+3], ii.w * aI[4*h+3]);
        }

        // ---- shifted radix-4 scan -> exclusive prefix v_in ----
        float x = __shfl_up_sync(FULL, iB, 1);
        if (lane == 0) x = 0.f;
        {
            float x1 = __shfl_up_sync(FULL, x, 1);
            float x2 = __shfl_up_sync(FULL, x, 2);
            float x3 = __shfl_up_sync(FULL, x, 3);
            x = fmaf(x3, c13, fmaf(x2, c12, fmaf(x1, c11, x)));
            x1 = __shfl_up_sync(FULL, x, 4);
            x2 = __shfl_up_sync(FULL, x, 8);
            x3 = __shfl_up_sync(FULL, x, 12);
            x = fmaf(x3, c23, fmaf(x2, c22, fmaf(x1, c21, x)));
            x1 = __shfl_up_sync(FULL, x, 16);
            x = fmaf(x1, c31, x);
        }
        const float v_in = x;

        // match states in place
        #pragma unroll
        for (int k = 0; k < 16; k++)
            aM[k] = em[k] * fmaf(dtcP[k], v_in, pre[k]);

        // flank states
        float nLF = eins * floop * aLF;
        float nU  = eins * (fmaf(ep0, mx, fbe0 * aLF) + (floop + fbe0) * aU);
        float nRF = eins * (fmaf(ep1, mx, fbe1 * (aLF + aU)) + floop * aRF);
        aLF = nLF; aU = nU; aRF = nRF;

        if (rescale) {
            float s = tp + aLF + aU + aRF + TINYF;
            float inv = 1.f / s;
            ll += logf(s);
            #pragma unroll
            for (int k = 0; k < 16; k++) { aM[k] *= inv; aI[k] *= inv; }
            aLF *= inv; aU *= inv; aRF *= inv;
        }
    }

    // ---- final mass -> log-likelihood ----
    {
        float tp = 0.f;
        #pragma unroll
        for (int k = 0; k < 16; k++) tp += aM[k] + aI[k];
        #pragma unroll
        for (int d = 16; d; d >>= 1) tp += __shfl_xor_sync(FULL, tp, d);
        float s = tp + aLF + aU + aRF + TINYF;
        ll += logf(s);
        if (lane == 0) out[b] = ll;
    }
}

extern "C" void kernel_launch(void* const* d_in, const int* in_sizes, int n_in,
                              void* d_out, int out_size)
{
    setup_kernel<<<1, 512>>>(
        (const float*)d_in[1],  (const float*)d_in[2],  (const float*)d_in[3],
        (const float*)d_in[4],  (const float*)d_in[5],  (const float*)d_in[6],
        (const float*)d_in[7],  (const float*)d_in[8],  (const float*)d_in[9],
        (const float*)d_in[10], (const float*)d_in[11], (const float*)d_in[12],
        (const float*)d_in[13], (const float*)d_in[14], (const float*)d_in[15],
        (const float*)d_in[16], (const float*)d_in[17]);
    fwd_kernel<<<128, 32>>>((const int*)d_in[0], (float*)d_out);
}

// round 10
// speedup vs baseline: 1.2521x; 1.2521x over previous
#include <cuda_runtime.h>
#include <math.h>

#define TINYF 1.17549435e-38f

// ---------------- precomputed HMM parameters (device globals) ----------------
__device__ __align__(16) float g_em[25 * 512];   // transposed match emissions [sym][m]
__device__ float g_insd[32];                     // insert/flank emission dist
__device__ __align__(16) float g_enter[512];
__device__ __align__(16) float g_mtm[512];       // mtm_p[m-1]
__device__ __align__(16) float g_i2m[512];       // i2m_p[m-1]
__device__ __align__(16) float g_dtm[512];       // dtm_p[m-1]
__device__ __align__(16) float g_m2e[512];       // m2e_tot[m]
__device__ __align__(16) float g_m2i[512];       // m2i_p[m]
__device__ __align__(16) float g_i2i[512];       // i2i_p[m]
__device__ __align__(16) float g_asc[512];       // scan mult dtd_p[m-1] (a_0 = 1)
__device__ __align__(16) float g_msc[512];       // scan coeff mtd_p[m]
__device__ float g_scal[8];                      // floop,fexit,be,ep0,ep1,p0

// ---------------- setup: build all derived parameters (1 block, 512 thr) ----
__global__ void setup_kernel(
    const float* __restrict__ em_kernel, const float* __restrict__ ins_kernel,
    const float* __restrict__ flank_kernel, const float* __restrict__ btm,
    const float* __restrict__ m2e, const float* __restrict__ mtm,
    const float* __restrict__ m2i, const float* __restrict__ i2m,
    const float* __restrict__ i2i, const float* __restrict__ mtd,
    const float* __restrict__ dtm, const float* __restrict__ dtd,
    const float* __restrict__ lf_loop, const float* __restrict__ lf_exit,
    const float* __restrict__ e2u, const float* __restrict__ e2r,
    const float* __restrict__ e2t)
{
    __shared__ float red[512];
    __shared__ float incl[512];
    int m = threadIdx.x;

    float dtmp_m1 = 0.f, dtdp_m1 = 0.f;
    if (m >= 1) {
        float a = dtm[m-1], b = dtd[m-1], mx = fmaxf(a, b);
        float ea = expf(a-mx), eb = expf(b-mx), z = ea+eb;
        dtmp_m1 = ea/z; dtdp_m1 = eb/z;
    }
    float dtdp_m = 0.f;
    if (m <= 510) {
        float a = dtm[m], b = dtd[m], mx = fmaxf(a, b);
        float ea = expf(a-mx), eb = expf(b-mx);
        dtdp_m = eb/(ea+eb);
    }
    float m2ip_m = 0.f, m2ep_m = 0.f, mtdp_next = 0.f;
    if (m <= 510) {
        float v0 = mtm[m], v1 = m2i[m], v2 = m2e[m], v3 = mtd[m+1];
        float mx = fmaxf(fmaxf(v0,v1), fmaxf(v2,v3));
        float e0 = expf(v0-mx), e1 = expf(v1-mx), e2 = expf(v2-mx), e3 = expf(v3-mx);
        float z = e0+e1+e2+e3;
        m2ip_m = e1/z; m2ep_m = e2/z; mtdp_next = e3/z;
    }
    float mtmp_m1 = 0.f, mtdp_m_mid = 0.f;
    if (m >= 1) {
        float v0 = mtm[m-1], v1 = m2i[m-1], v2 = m2e[m-1], v3 = mtd[m];
        float mx = fmaxf(fmaxf(v0,v1), fmaxf(v2,v3));
        float e0 = expf(v0-mx), e1 = expf(v1-mx), e2 = expf(v2-mx), e3 = expf(v3-mx);
        float z = e0+e1+e2+e3;
        mtmp_m1 = e0/z; mtdp_m_mid = e3/z;
    }
    float i2ip_m = 0.f;
    if (m <= 510) {
        float a = i2m[m], b = i2i[m], mx = fmaxf(a, b);
        float ea = expf(a-mx), eb = expf(b-mx);
        i2ip_m = eb/(ea+eb);
    }
    float i2mp_m1 = 0.f;
    if (m >= 1) {
        float a = i2m[m-1], b = i2i[m-1], mx = fmaxf(a, b);
        float ea = expf(a-mx), eb = expf(b-mx);
        i2mp_m1 = ea/(ea+eb);
    }

    // begin softmax over [btm(512), mtd[0]]
    float bx = btm[m];
    red[m] = bx; __syncthreads();
    for (int s = 256; s > 0; s >>= 1) { if (m < s) red[m] = fmaxf(red[m], red[m+s]); __syncthreads(); }
    float bmx = fmaxf(red[0], mtd[0]);
    __syncthreads();
    float bex = expf(bx - bmx);
    red[m] = bex; __syncthreads();
    for (int s = 256; s > 0; s >>= 1) { if (m < s) red[m] += red[m+s]; __syncthreads(); }
    float bz = red[0] + expf(mtd[0] - bmx);
    __syncthreads();
    float btmp_m  = bex / bz;
    float mtd_p0  = expf(mtd[0] - bmx) / bz;

    // cp prefix sum
    incl[m] = (m <= 510) ? logf(dtdp_m) : 0.f;
    __syncthreads();
    for (int d = 1; d < 512; d <<= 1) {
        float v = incl[m];
        float add = (m >= d) ? incl[m-d] : 0.f;
        __syncthreads();
        incl[m] = v + add;
        __syncthreads();
    }
    float cp511 = incl[510];
    float cpm1  = (m >= 2) ? incl[m-2] : 0.f;
    float cpp1  = incl[m];
    float be = mtd_p0 * expf(cp511);
    float enter_m = btmp_m + ((m >= 1) ? mtd_p0 * expf(cpm1) * dtmp_m1 : 0.f);
    float m2etot = (m <= 510) ? (m2ep_m + mtdp_next * expf(cp511 - cpp1)) : 1.f;
    float mtdp_m = (m == 0) ? mtd_p0 : mtdp_m_mid;

    g_enter[m] = enter_m;
    g_mtm[m]   = mtmp_m1;
    g_i2m[m]   = i2mp_m1;
    g_dtm[m]   = (m >= 1) ? dtmp_m1 : 0.f;
    g_m2e[m]   = m2etot;
    g_m2i[m]   = m2ip_m;
    g_i2i[m]   = i2ip_m;
    g_asc[m]   = (m >= 1) ? dtdp_m1 : 1.f;
    g_msc[m]   = mtdp_m;

    {
        const float* row = em_kernel + m * 25;
        float mxr = row[0];
        for (int s = 1; s < 25; s++) mxr = fmaxf(mxr, row[s]);
        float z = 0.f;
        for (int s = 0; s < 25; s++) z += expf(row[s] - mxr);
        float invz = 1.f / z;
        for (int s = 0; s < 25; s++) g_em[s * 512 + m] = expf(row[s] - mxr) * invz;
    }
    if (m == 0) {
        float mxi = ins_kernel[0];
        for (int s = 1; s < 25; s++) mxi = fmaxf(mxi, ins_kernel[s]);
        float z = 0.f;
        for (int s = 0; s < 25; s++) z += expf(ins_kernel[s] - mxi);
        for (int s = 0; s < 25; s++) g_insd[s] = expf(ins_kernel[s] - mxi) / z;
        float a = lf_loop[0], b = lf_exit[0], mx = fmaxf(a, b);
        float ea = expf(a-mx), eb = expf(b-mx), z2 = ea+eb;
        float u = e2u[0], r = e2r[0], t = e2t[0];
        float mxe = fmaxf(fmaxf(u, r), t);
        float eu = expf(u-mxe), er = expf(r-mxe), et = expf(t-mxe);
        float ze = eu + er + et;
        g_scal[0] = ea/z2;  // floop
        g_scal[1] = eb/z2;  // fexit
        g_scal[2] = be;
        g_scal[3] = eu/ze;  // ep0
        g_scal[4] = er/ze;  // ep1
        g_scal[5] = 1.f / (1.f + expf(-flank_kernel[0]));  // p0
    }
}

// transposed-float4 smem layout: elem k of lane l at [(k>>2)*128 + l*4 + (k&3)]
#define SM_IDX(k, l) (((k) >> 2) * 128 + (l) * 4 + ((k) & 3))

// ---------------- forward kernel: 1 CTA = 1 warp per batch, 16 states/lane --
__global__ __launch_bounds__(32, 1)
void fwd_kernel(const int* __restrict__ seq, float* __restrict__ out)
{
    __shared__ int   s_seq[1024];
    __shared__ float s_insd[32];
    __shared__ __align__(16) float s_en[512], s_mtc[512], s_i2mc[512];
    __shared__ __align__(16) float s_mec[512], s_mic[512], s_iic[512];

    const int lane = threadIdx.x;
    const int b = blockIdx.x;
    const int m0 = lane * 16;
    const unsigned FULL = 0xffffffffu;

    // stage sequence + insert dist + transposed coefficient arrays
    {
        const int4* sp = (const int4*)(seq + b * 1024);
        #pragma unroll
        for (int k = 0; k < 8; k++)
            ((int4*)s_seq)[lane + 32 * k] = sp[lane + 32 * k];
        if (lane < 25) s_insd[lane] = g_insd[lane];
        for (int idx = lane; idx < 512; idx += 32) {
            int kk = idx & 15, ln = idx >> 4;
            s_en  [SM_IDX(kk, ln)] = g_enter[idx];
            s_mtc [SM_IDX(kk, ln)] = g_mtm[idx];
            s_i2mc[SM_IDX(kk, ln)] = g_i2m[idx];
            s_mec [SM_IDX(kk, ln)] = g_m2e[idx];
            s_mic [SM_IDX(kk, ln)] = g_m2i[idx];
            s_iic [SM_IDX(kk, ln)] = g_i2i[idx];
        }
    }

    // hot per-thread constants
    float dtcP[16], mscP[16];
    float cU, mscP0, cUm1z, segA;
    {
        float asc[16], msc[16], dtc[16];
        #pragma unroll
        for (int h = 0; h < 4; h++) {
            float4 v;
            v = *(const float4*)(g_asc + m0 + 4*h); asc[4*h]=v.x; asc[4*h+1]=v.y; asc[4*h+2]=v.z; asc[4*h+3]=v.w;
            v = *(const float4*)(g_msc + m0 + 4*h); msc[4*h]=v.x; msc[4*h+1]=v.y; msc[4*h+2]=v.z; msc[4*h+3]=v.w;
            v = *(const float4*)(g_dtm + m0 + 4*h); dtc[4*h]=v.x; dtc[4*h+1]=v.y; dtc[4*h+2]=v.z; dtc[4*h+3]=v.w;
        }
        float P[16];
        P[0] = asc[0];
        #pragma unroll
        for (int k = 1; k < 16; k++) P[k] = P[k-1] * asc[k];
        #pragma unroll
        for (int k = 0; k < 16; k++) mscP[k] = msc[k] / P[k];
        dtcP[0] = dtc[0];
        #pragma unroll
        for (int k = 1; k < 16; k++) dtcP[k] = dtc[k] * P[k-1];
        segA = P[15]; cU = P[15]; mscP0 = mscP[0];
        float cUm = cU * mscP0;
        cUm1z = __shfl_up_sync(FULL, cUm, 1);
        if (lane < 2) cUm1z = 0.f;
    }

    const float floop = g_scal[0], fexit = g_scal[1], be = g_scal[2];
    const float ep0 = g_scal[3], ep1 = g_scal[4], p0 = g_scal[5];
    const float fbe0 = fexit * be * ep0, fbe1 = fexit * be * ep1;

    // radix-4 scan constants on the SHIFTED per-lane A
    float c11, c12, c13, c21, c22, c23, c31;
    {
        float As = __shfl_up_sync(FULL, segA, 1);
        if (lane == 0) As = 1.f;
        float a1 = __shfl_up_sync(FULL, As, 1);
        float a2 = __shfl_up_sync(FULL, As, 2);
        float a3 = __shfl_up_sync(FULL, As, 3);
        c11 = (lane >= 1) ? As : 0.f;
        c12 = (lane >= 2) ? As * a1 : 0.f;
        c13 = (lane >= 3) ? As * a1 * a2 : 0.f;
        float G1 = As;
        if (lane >= 1) G1 *= a1;
        if (lane >= 2) G1 *= a2;
        if (lane >= 3) G1 *= a3;
        float g1 = __shfl_up_sync(FULL, G1, 4);
        float g2 = __shfl_up_sync(FULL, G1, 8);
        float g3 = __shfl_up_sync(FULL, G1, 12);
        c21 = (lane >= 4)  ? G1 : 0.f;
        c22 = (lane >= 8)  ? G1 * g1 : 0.f;
        c23 = (lane >= 12) ? G1 * g1 * g2 : 0.f;
        float G2 = G1;
        if (lane >= 4)  G2 *= g1;
        if (lane >= 8)  G2 *= g2;
        if (lane >= 12) G2 *= g3;
        c31 = (lane >= 16) ? G2 : 0.f;
    }
    __syncwarp();

    // ---- t = 0 init ----
    int c = s_seq[0];
    float eins0 = s_insd[c];
    float aM[16], aI[16], em[16], pre[16], q[15];
    #pragma unroll
    for (int h = 0; h < 4; h++) {
        float4 ev = __ldg((const float4*)(g_em + c * 512 + m0 + 4*h));
        em[4*h]=ev.x; em[4*h+1]=ev.y; em[4*h+2]=ev.z; em[4*h+3]=ev.w;
    }
    const float q0 = 1.f - p0;
    #pragma unroll
    for (int h = 0; h < 4; h++) {
        float4 env = *(const float4*)(s_en + h*128 + lane*4);
        aM[4*h]   = q0 * env.x * em[4*h];
        aM[4*h+1] = q0 * env.y * em[4*h+1];
        aM[4*h+2] = q0 * env.z * em[4*h+2];
        aM[4*h+3] = q0 * env.w * em[4*h+3];
        aI[4*h] = 0.f; aI[4*h+1] = 0.f; aI[4*h+2] = 0.f; aI[4*h+3] = 0.f;
    }
    float aLF = p0 * eins0, aU = q0 * be * ep0 * eins0, aRF = q0 * be * ep1 * eins0;
    float ll;
    {
        float tp = 0.f;
        #pragma unroll
        for (int k = 0; k < 16; k++) tp += aM[k];
        #pragma unroll
        for (int d = 16; d; d >>= 1) tp += __shfl_xor_sync(FULL, tp, d);
        float s = tp + aLF + aU + aRF + TINYF;
        float inv = 1.f / s; ll = logf(s);
        #pragma unroll
        for (int k = 0; k < 16; k++) aM[k] *= inv;
        aLF *= inv; aU *= inv; aRF *= inv;
    }

    // ---- priming: mx(0), fc(1), pre(1), x(1), aI(1), em(1) ----
    float mxprev;
    {
        float mx = 0.f;
        #pragma unroll
        for (int h = 0; h < 4; h++) {
            float4 me = *(const float4*)(s_mec + h*128 + lane*4);
            mx = fmaf(me.x, aM[4*h], mx);
            mx = fmaf(me.y, aM[4*h+1], mx);
            mx = fmaf(me.z, aM[4*h+2], mx);
            mx = fmaf(me.w, aM[4*h+3], mx);
        }
        #pragma unroll
        for (int d = 16; d; d >>= 1) mx += __shfl_xor_sync(FULL, mx, d);
        mxprev = mx;
    }
    float x;
    {
        float fc1 = fexit * (aLF + aU);
        float prevM = __shfl_up_sync(FULL, aM[15], 1);
        float prevI = 0.f;
        if (lane == 0) prevM = 0.f;
        #pragma unroll
        for (int j = 0; j < 15; j++) q[j] = aM[j] * mscP[j+1];
        float u = mscP0 * prevM;
        #pragma unroll
        for (int h = 0; h < 4; h++) {
            float4 env = *(const float4*)(s_en  + h*128 + lane*4);
            float4 mtv = *(const float4*)(s_mtc + h*128 + lane*4);
            float4 i2v = *(const float4*)(s_i2mc+ h*128 + lane*4);
            #pragma unroll
            for (int j = 0; j < 4; j++) {
                int k = 4*h + j;
                float enk = (&env.x)[j], mtk = (&mtv.x)[j], i2k = (&i2v.x)[j];
                float am1 = (k == 0) ? prevM : aM[k-1];
                float ai1 = (k == 0) ? prevI : aI[k-1];
                if (k == 0) {
                    pre[0] = fmaf(i2k, ai1, fmaf(mtk, am1, enk * fc1));
                } else {
                    pre[k] = fmaf(dtcP[k], u,
                             fmaf(i2k, ai1, fmaf(mtk, am1, enk * fc1)));
                    u += q[k-1];
                }
            }
        }
        // x(1)
        float s01=q[0]+q[1], s23=q[2]+q[3], s45=q[4]+q[5], s67=q[6]+q[7];
        float s89=q[8]+q[9], sab=q[10]+q[11], scd=q[12]+q[13];
        float t0=s01+s23, t1=s45+s67, t2=s89+sab, t3=scd+q[14];
        float tot = (t0+t1) + (t2+t3);
        float y  = cU * tot;
        float y1 = __shfl_up_sync(FULL, y, 1);
        float a2 = __shfl_up_sync(FULL, aM[15], 2);
        float xn = fmaf(cUm1z, a2, y1);
        x = (lane == 0) ? 0.f : xn;
    }
    float einsK = s_insd[s_seq[1]];
    c = s_seq[1];
    #pragma unroll
    for (int h = 0; h < 4; h++) {
        float4 ev = __ldg((const float4*)(g_em + c * 512 + m0 + 4*h));
        em[4*h]=ev.x; em[4*h+1]=ev.y; em[4*h+2]=ev.z; em[4*h+3]=ev.w;
    }
    #pragma unroll
    for (int h = 0; h < 4; h++) {
        float4 miv = *(const float4*)(s_mic + h*128 + lane*4);
        aI[4*h]   = einsK * miv.x * aM[4*h];
        aI[4*h+1] = einsK * miv.y * aM[4*h+1];
        aI[4*h+2] = einsK * miv.z * aM[4*h+2];
        aI[4*h+3] = einsK * miv.w * aM[4*h+3];
    }
    float invR = 1.f;

    // ---- main recurrence ----
    for (int t = 1; t < 1024; t++) {
        // -- on-chain: scan, aM, next x --
        float v;
        {
            float x1 = __shfl_up_sync(FULL, x, 1);
            float x2 = __shfl_up_sync(FULL, x, 2);
            float x3 = __shfl_up_sync(FULL, x, 3);
            x = fmaf(x3, c13, fmaf(x2, c12, fmaf(x1, c11, x)));
            x1 = __shfl_up_sync(FULL, x, 4);
            x2 = __shfl_up_sync(FULL, x, 8);
            x3 = __shfl_up_sync(FULL, x, 12);
            x = fmaf(x3, c23, fmaf(x2, c22, fmaf(x1, c21, x)));
            x1 = __shfl_up_sync(FULL, x, 16);
            v = fmaf(x1, c31, x);
        }
        #pragma unroll
        for (int k = 0; k < 16; k++)
            aM[k] = em[k] * fmaf(dtcP[k], v, pre[k]);
        #pragma unroll
        for (int j = 0; j < 15; j++) q[j] = aM[j] * mscP[j+1];
        {
            float s01=q[0]+q[1], s23=q[2]+q[3], s45=q[4]+q[5], s67=q[6]+q[7];
            float s89=q[8]+q[9], sab=q[10]+q[11], scd=q[12]+q[13];
            float t0=s01+s23, t1=s45+s67, t2=s89+sab, t3=scd+q[14];
            float tot = (t0+t1) + (t2+t3);
            float y  = cU * tot;
            float y1 = __shfl_up_sync(FULL, y, 1);
            float a2 = __shfl_up_sync(FULL, aM[15], 2);
            float xn = fmaf(cUm1z, a2, y1);
            x = (lane == 0) ? 0.f : xn;
        }

        // -- tail (off-chain) --
        // flanks(t) from flanks(t-1), mx(t-1)
        {
            float nLF = einsK * floop * aLF;
            float nU  = einsK * (fmaf(ep0, mxprev, fbe0 * aLF) + (floop + fbe0) * aU);
            float nRF = einsK * (fmaf(ep1, mxprev, fbe1 * (aLF + aU)) + floop * aRF);
            aLF = nLF; aU = nU; aRF = nRF;
        }
        float fcn = fexit * (aLF + aU);
        // mx(t)
        {
            float mx = 0.f;
            #pragma unroll
            for (int h = 0; h < 4; h++) {
                float4 me = *(const float4*)(s_mec + h*128 + lane*4);
                mx = fmaf(me.x, aM[4*h], mx);
                mx = fmaf(me.y, aM[4*h+1], mx);
                mx = fmaf(me.z, aM[4*h+2], mx);
                mx = fmaf(me.w, aM[4*h+3], mx);
            }
            #pragma unroll
            for (int d = 16; d; d >>= 1) mx += __shfl_xor_sync(FULL, mx, d);
            mxprev = mx;
        }
        // measure total every 8 steps (applied 4 steps later)
        if ((t & 7) == 0) {
            float tp = 0.f;
            #pragma unroll
            for (int k = 0; k < 16; k++) tp += aM[k] + aI[k];
            #pragma unroll
            for (int d = 16; d; d >>= 1) tp += __shfl_xor_sync(FULL, tp, d);
            float s = tp + aLF + aU + aRF + TINYF;
            invR = 1.f / s;
            ll += logf(s);
        }
        if (t < 1023) {
            float prevM = __shfl_up_sync(FULL, aM[15], 1);
            float prevI = __shfl_up_sync(FULL, aI[15], 1);
            if (lane == 0) { prevM = 0.f; prevI = 0.f; }
            float u = mscP0 * prevM;
            #pragma unroll
            for (int h = 0; h < 4; h++) {
                float4 env = *(const float4*)(s_en  + h*128 + lane*4);
                float4 mtv = *(const float4*)(s_mtc + h*128 + lane*4);
                float4 i2v = *(const float4*)(s_i2mc+ h*128 + lane*4);
                #pragma unroll
                for (int j = 0; j < 4; j++) {
                    int k = 4*h + j;
                    float enk = (&env.x)[j], mtk = (&mtv.x)[j], i2k = (&i2v.x)[j];
                    float am1 = (k == 0) ? prevM : aM[k-1];
                    float ai1 = (k == 0) ? prevI : aI[k-1];
                    if (k == 0) {
                        pre[0] = fmaf(i2k, ai1, fmaf(mtk, am1, enk * fcn));
                    } else {
                        pre[k] = fmaf(dtcP[k], u,
                                 fmaf(i2k, ai1, fmaf(mtk, am1, enk * fcn)));
                        u += q[k-1];
                    }
                }
            }
            float eK1 = s_insd[s_seq[t+1]];
            if ((t & 7) == 3) {   // apply the 4-step-stale rescale to state(t+1)
                #pragma unroll
                for (int k = 0; k < 16; k++) pre[k] *= invR;
                x *= invR;
                eK1 *= invR;
            }
            c = s_seq[t+1];
            #pragma unroll
            for (int h = 0; h < 4; h++) {
                float4 ev = __ldg((const float4*)(g_em + c * 512 + m0 + 4*h));
                em[4*h]=ev.x; em[4*h+1]=ev.y; em[4*h+2]=ev.z; em[4*h+3]=ev.w;
            }
            #pragma unroll
            for (int h = 0; h < 4; h++) {
                float4 miv = *(const float4*)(s_mic + h*128 + lane*4);
                float4 iiv = *(const float4*)(s_iic + h*128 + lane*4);
                aI[4*h]   = eK1 * fmaf(miv.x, aM[4*h],   iiv.x * aI[4*h]);
                aI[4*h+1] = eK1 * fmaf(miv.y, aM[4*h+1], iiv.y * aI[4*h+1]);
                aI[4*h+2] = eK1 * fmaf(miv.z, aM[4*h+2], iiv.z * aI[4*h+2]);
                aI[4*h+3] = eK1 * fmaf(miv.w, aM[4*h+3], iiv.w * aI[4*h+3]);
            }
            einsK = eK1;
        }
    }

    // ---- final mass -> log-likelihood ----
    {
        float tp = 0.f;
        #pragma unroll
        for (int k = 0; k < 16; k++) tp += aM[k] + aI[k];
        #pragma unroll
        for (int d = 16; d; d >>= 1) tp += __shfl_xor_sync(FULL, tp, d);
        float s = tp + aLF + aU + aRF + TINYF;
        ll += logf(s);
        if (lane == 0) out[b] = ll;
    }
}

extern "C" void kernel_launch(void* const* d_in, const int* in_sizes, int n_in,
                              void* d_out, int out_size)
{
    setup_kernel<<<1, 512>>>(
        (const float*)d_in[1],  (const float*)d_in[2],  (const float*)d_in[3],
        (const float*)d_in[4],  (const float*)d_in[5],  (const float*)d_in[6],
        (const float*)d_in[7],  (const float*)d_in[8],  (const float*)d_in[9],
        (const float*)d_in[10], (const float*)d_in[11], (const float*)d_in[12],
        (const float*)d_in[13], (const float*)d_in[14], (const float*)d_in[15],
        (const float*)d_in[16], (const float*)d_in[17]);
    fwd_kernel<<<128, 32>>>((const int*)d_in[0], (float*)d_out);
}

// round 11
// speedup vs baseline: 1.5965x; 1.2750x over previous
#include <cuda_runtime.h>
#include <math.h>

#define TINYF 1.17549435e-38f

// ---------------- precomputed HMM parameters (device globals) ----------------
__device__ __align__(16) float g_em[25 * 512];   // transposed match emissions [sym][m]
__device__ float g_insd[32];                     // insert/flank emission dist
__device__ __align__(16) float g_enter[512];
__device__ __align__(16) float g_mtm[512];       // mtm_p[m-1]
__device__ __align__(16) float g_i2m[512];       // i2m_p[m-1]
__device__ __align__(16) float g_dtm[512];       // dtm_p[m-1]
__device__ __align__(16) float g_m2e[512];       // m2e_tot[m]
__device__ __align__(16) float g_m2i[512];       // m2i_p[m]
__device__ __align__(16) float g_i2i[512];       // i2i_p[m]
__device__ __align__(16) float g_asc[512];       // scan mult dtd_p[m-1] (a_0 = 1)
__device__ __align__(16) float g_msc[512];       // scan coeff mtd_p[m]
__device__ float g_scal[8];                      // floop,fexit,be,ep0,ep1,p0

// ---------------- setup: build all derived parameters (1 block, 512 thr) ----
__global__ void setup_kernel(
    const float* __restrict__ em_kernel, const float* __restrict__ ins_kernel,
    const float* __restrict__ flank_kernel, const float* __restrict__ btm,
    const float* __restrict__ m2e, const float* __restrict__ mtm,
    const float* __restrict__ m2i, const float* __restrict__ i2m,
    const float* __restrict__ i2i, const float* __restrict__ mtd,
    const float* __restrict__ dtm, const float* __restrict__ dtd,
    const float* __restrict__ lf_loop, const float* __restrict__ lf_exit,
    const float* __restrict__ e2u, const float* __restrict__ e2r,
    const float* __restrict__ e2t)
{
    __shared__ float red[512];
    __shared__ float incl[512];
    int m = threadIdx.x;

    float dtmp_m1 = 0.f, dtdp_m1 = 0.f;
    if (m >= 1) {
        float a = dtm[m-1], b = dtd[m-1], mx = fmaxf(a, b);
        float ea = expf(a-mx), eb = expf(b-mx), z = ea+eb;
        dtmp_m1 = ea/z; dtdp_m1 = eb/z;
    }
    float dtdp_m = 0.f;
    if (m <= 510) {
        float a = dtm[m], b = dtd[m], mx = fmaxf(a, b);
        float ea = expf(a-mx), eb = expf(b-mx);
        dtdp_m = eb/(ea+eb);
    }
    float m2ip_m = 0.f, m2ep_m = 0.f, mtdp_next = 0.f;
    if (m <= 510) {
        float v0 = mtm[m], v1 = m2i[m], v2 = m2e[m], v3 = mtd[m+1];
        float mx = fmaxf(fmaxf(v0,v1), fmaxf(v2,v3));
        float e0 = expf(v0-mx), e1 = expf(v1-mx), e2 = expf(v2-mx), e3 = expf(v3-mx);
        float z = e0+e1+e2+e3;
        m2ip_m = e1/z; m2ep_m = e2/z; mtdp_next = e3/z;
    }
    float mtmp_m1 = 0.f, mtdp_m_mid = 0.f;
    if (m >= 1) {
        float v0 = mtm[m-1], v1 = m2i[m-1], v2 = m2e[m-1], v3 = mtd[m];
        float mx = fmaxf(fmaxf(v0,v1), fmaxf(v2,v3));
        float e0 = expf(v0-mx), e1 = expf(v1-mx), e2 = expf(v2-mx), e3 = expf(v3-mx);
        float z = e0+e1+e2+e3;
        mtmp_m1 = e0/z; mtdp_m_mid = e3/z;
    }
    float i2ip_m = 0.f;
    if (m <= 510) {
        float a = i2m[m], b = i2i[m], mx = fmaxf(a, b);
        float ea = expf(a-mx), eb = expf(b-mx);
        i2ip_m = eb/(ea+eb);
    }
    float i2mp_m1 = 0.f;
    if (m >= 1) {
        float a = i2m[m-1], b = i2i[m-1], mx = fmaxf(a, b);
        float ea = expf(a-mx), eb = expf(b-mx);
        i2mp_m1 = ea/(ea+eb);
    }

    float bx = btm[m];
    red[m] = bx; __syncthreads();
    for (int s = 256; s > 0; s >>= 1) { if (m < s) red[m] = fmaxf(red[m], red[m+s]); __syncthreads(); }
    float bmx = fmaxf(red[0], mtd[0]);
    __syncthreads();
    float bex = expf(bx - bmx);
    red[m] = bex; __syncthreads();
    for (int s = 256; s > 0; s >>= 1) { if (m < s) red[m] += red[m+s]; __syncthreads(); }
    float bz = red[0] + expf(mtd[0] - bmx);
    __syncthreads();
    float btmp_m  = bex / bz;
    float mtd_p0  = expf(mtd[0] - bmx) / bz;

    incl[m] = (m <= 510) ? logf(dtdp_m) : 0.f;
    __syncthreads();
    for (int d = 1; d < 512; d <<= 1) {
        float v = incl[m];
        float add = (m >= d) ? incl[m-d] : 0.f;
        __syncthreads();
        incl[m] = v + add;
        __syncthreads();
    }
    float cp511 = incl[510];
    float cpm1  = (m >= 2) ? incl[m-2] : 0.f;
    float cpp1  = incl[m];
    float be = mtd_p0 * expf(cp511);
    float enter_m = btmp_m + ((m >= 1) ? mtd_p0 * expf(cpm1) * dtmp_m1 : 0.f);
    float m2etot = (m <= 510) ? (m2ep_m + mtdp_next * expf(cp511 - cpp1)) : 1.f;
    float mtdp_m = (m == 0) ? mtd_p0 : mtdp_m_mid;

    g_enter[m] = enter_m;
    g_mtm[m]   = mtmp_m1;
    g_i2m[m]   = i2mp_m1;
    g_dtm[m]   = (m >= 1) ? dtmp_m1 : 0.f;
    g_m2e[m]   = m2etot;
    g_m2i[m]   = m2ip_m;
    g_i2i[m]   = i2ip_m;
    g_asc[m]   = (m >= 1) ? dtdp_m1 : 1.f;
    g_msc[m]   = mtdp_m;

    {
        const float* row = em_kernel + m * 25;
        float mxr = row[0];
        for (int s = 1; s < 25; s++) mxr = fmaxf(mxr, row[s]);
        float z = 0.f;
        for (int s = 0; s < 25; s++) z += expf(row[s] - mxr);
        float invz = 1.f / z;
        for (int s = 0; s < 25; s++) g_em[s * 512 + m] = expf(row[s] - mxr) * invz;
    }
    if (m == 0) {
        float mxi = ins_kernel[0];
        for (int s = 1; s < 25; s++) mxi = fmaxf(mxi, ins_kernel[s]);
        float z = 0.f;
        for (int s = 0; s < 25; s++) z += expf(ins_kernel[s] - mxi);
        for (int s = 0; s < 25; s++) g_insd[s] = expf(ins_kernel[s] - mxi) / z;
        float a = lf_loop[0], b = lf_exit[0], mx = fmaxf(a, b);
        float ea = expf(a-mx), eb = expf(b-mx), z2 = ea+eb;
        float u = e2u[0], r = e2r[0], t = e2t[0];
        float mxe = fmaxf(fmaxf(u, r), t);
        float eu = expf(u-mxe), er = expf(r-mxe), et = expf(t-mxe);
        float ze = eu + er + et;
        g_scal[0] = ea/z2;
        g_scal[1] = eb/z2;
        g_scal[2] = be;
        g_scal[3] = eu/ze;
        g_scal[4] = er/ze;
        g_scal[5] = 1.f / (1.f + expf(-flank_kernel[0]));
    }
}

// transposed smem layout for 64 threads, 8 elems each
#define SMX(k, l) (((k) >> 2) * 256 + (l) * 4 + ((k) & 3))

struct Buf { float wB0; float nbM, nbI; float mx[2]; float tot[2]; };

// ---------------- forward kernel: 1 CTA per batch, 64 threads, 2 warps ------
__global__ __launch_bounds__(64, 1)
void fwd_kernel(const int* __restrict__ seq, float* __restrict__ out)
{
    __shared__ int   s_seq[1024];
    __shared__ float s_insd[32];
    __shared__ __align__(16) float s_en[512], s_mtc[512], s_i2mc[512];
    __shared__ __align__(16) float s_mec[512], s_mic[512], s_iic[512];
    __shared__ Buf   s_b[2];

    const int tid = threadIdx.x, lane = tid & 31, warp = tid >> 5;
    const int b = blockIdx.x;
    const int m0 = tid * 8;
    const unsigned FULL = 0xffffffffu;

    {
        const int4* sp = (const int4*)(seq + b * 1024);
        #pragma unroll
        for (int k = 0; k < 4; k++)
            ((int4*)s_seq)[tid + 64 * k] = sp[tid + 64 * k];
        if (tid < 25) s_insd[tid] = g_insd[tid];
        for (int idx = tid; idx < 512; idx += 64) {
            int kk = idx & 7, ln = idx >> 3;
            s_en  [SMX(kk, ln)] = g_enter[idx];
            s_mtc [SMX(kk, ln)] = g_mtm[idx];
            s_i2mc[SMX(kk, ln)] = g_i2m[idx];
            s_mec [SMX(kk, ln)] = g_m2e[idx];
            s_mic [SMX(kk, ln)] = g_m2i[idx];
            s_iic [SMX(kk, ln)] = g_i2i[idx];
        }
    }

    // hot per-thread constants
    float dtcP[8], mscP[8];
    float cU, cUm, cUm1z, segA, mscP0, mt0, i20;
    {
        float asc[8], msc[8], dtc[8];
        #pragma unroll
        for (int h = 0; h < 2; h++) {
            float4 v;
            v = *(const float4*)(g_asc + m0 + 4*h); asc[4*h]=v.x; asc[4*h+1]=v.y; asc[4*h+2]=v.z; asc[4*h+3]=v.w;
            v = *(const float4*)(g_msc + m0 + 4*h); msc[4*h]=v.x; msc[4*h+1]=v.y; msc[4*h+2]=v.z; msc[4*h+3]=v.w;
            v = *(const float4*)(g_dtm + m0 + 4*h); dtc[4*h]=v.x; dtc[4*h+1]=v.y; dtc[4*h+2]=v.z; dtc[4*h+3]=v.w;
        }
        float P[8];
        P[0] = asc[0];
        #pragma unroll
        for (int k = 1; k < 8; k++) P[k] = P[k-1] * asc[k];
        #pragma unroll
        for (int k = 0; k < 8; k++) mscP[k] = msc[k] / P[k];
        dtcP[0] = dtc[0];
        #pragma unroll
        for (int k = 1; k < 8; k++) dtcP[k] = dtc[k] * P[k-1];
        segA = P[7]; cU = P[7]; mscP0 = mscP[0];
        cUm = cU * mscP0;
        cUm1z = __shfl_up_sync(FULL, cUm, 1);
        if (lane < 2) cUm1z = 0.f;
        mt0 = g_mtm[m0]; i20 = g_i2m[m0];
    }

    const float floop = g_scal[0], fexit = g_scal[1], be = g_scal[2];
    const float ep0 = g_scal[3], ep1 = g_scal[4], p0 = g_scal[5];
    const float fbe0 = fexit * be * ep0, fbe1 = fexit * be * ep1;
    const float Kown = (warp == 1) ? (g_msc[256] / g_asc[256]) : 0.f;

    // radix-4 scan constants on the SHIFTED per-lane A, plus eAc
    float c11, c12, c13, c21, c22, c23, c31, eAc;
    {
        float As = __shfl_up_sync(FULL, segA, 1);
        if (lane == 0) As = 1.f;
        float a1 = __shfl_up_sync(FULL, As, 1);
        float a2 = __shfl_up_sync(FULL, As, 2);
        float a3 = __shfl_up_sync(FULL, As, 3);
        c11 = (lane >= 1) ? As : 0.f;
        c12 = (lane >= 2) ? As * a1 : 0.f;
        c13 = (lane >= 3) ? As * a1 * a2 : 0.f;
        float G1 = As;
        if (lane >= 1) G1 *= a1;
        if (lane >= 2) G1 *= a2;
        if (lane >= 3) G1 *= a3;
        float g1 = __shfl_up_sync(FULL, G1, 4);
        float g2 = __shfl_up_sync(FULL, G1, 8);
        float g3 = __shfl_up_sync(FULL, G1, 12);
        c21 = (lane >= 4)  ? G1 : 0.f;
        c22 = (lane >= 8)  ? G1 * g1 : 0.f;
        c23 = (lane >= 12) ? G1 * g1 * g2 : 0.f;
        float G2 = G1;
        if (lane >= 4)  G2 *= g1;
        if (lane >= 8)  G2 *= g2;
        if (lane >= 12) G2 *= g3;
        c31 = (lane >= 16) ? G2 : 0.f;
        float h1 = __shfl_up_sync(FULL, G2, 16);
        float G3 = G2;
        if (lane >= 16) G3 *= h1;
        eAc = G3;
    }
    __syncthreads();

    // ---- t = 0 init ----
    float aM[8], aI[8], em[8], pre[8], q[7];
    int c = s_seq[0];
    float eins0 = s_insd[c];
    {
        float4 ea = __ldg((const float4*)(g_em + c * 512 + m0));
        float4 eb = __ldg((const float4*)(g_em + c * 512 + m0 + 4));
        em[0]=ea.x; em[1]=ea.y; em[2]=ea.z; em[3]=ea.w;
        em[4]=eb.x; em[5]=eb.y; em[6]=eb.z; em[7]=eb.w;
    }
    const float q0f = 1.f - p0;
    {
        float4 e0 = *(const float4*)(s_en + tid*4);
        float4 e1 = *(const float4*)(s_en + 256 + tid*4);
        float env[8] = {e0.x,e0.y,e0.z,e0.w,e1.x,e1.y,e1.z,e1.w};
        #pragma unroll
        for (int k = 0; k < 8; k++) { aM[k] = q0f * env[k] * em[k]; aI[k] = 0.f; }
    }
    float aLF = p0 * eins0, aU = q0f * be * ep0 * eins0, aRF = q0f * be * ep1 * eins0;
    float ll;
    {
        float tp = 0.f;
        #pragma unroll
        for (int k = 0; k < 8; k++) tp += aM[k];
        #pragma unroll
        for (int d = 16; d; d >>= 1) tp += __shfl_xor_sync(FULL, tp, d);
        if (lane == 0) s_b[0].tot[warp] = tp;
        __syncthreads();
        float s = s_b[0].tot[0] + s_b[0].tot[1] + aLF + aU + aRF + TINYF;
        float inv = 1.f / s; ll = logf(s);
        #pragma unroll
        for (int k = 0; k < 8; k++) aM[k] *= inv;
        aLF *= inv; aU *= inv; aRF *= inv;
        __syncthreads();
    }

    // ---- priming for t=1 ----
    float x, iBown, einsK, invR = 1.f, flsave = 0.f;
    {
        #pragma unroll
        for (int j = 0; j < 7; j++) q[j] = aM[j] * mscP[j+1];
        float toty = ((q[0]+q[1]) + (q[2]+q[3])) + ((q[4]+q[5]) + q[6]);
        float y = cU * toty;
        float al1 = __shfl_up_sync(FULL, aM[7], 1);
        float y1  = __shfl_up_sync(FULL, y, 1);
        float a2  = __shfl_up_sync(FULL, aM[7], 2);
        iBown = fmaf(cUm, al1, y);
        x = (lane == 0) ? 0.f : fmaf(cUm1z, a2, y1);
        // mx(0)
        float mx = 0.f;
        {
            float4 me0 = *(const float4*)(s_mec + tid*4);
            float4 me1 = *(const float4*)(s_mec + 256 + tid*4);
            mx = me0.x*aM[0]+me0.y*aM[1]+me0.z*aM[2]+me0.w*aM[3]
               + me1.x*aM[4]+me1.y*aM[5]+me1.z*aM[6]+me1.w*aM[7];
        }
        #pragma unroll
        for (int d = 16; d; d >>= 1) mx += __shfl_xor_sync(FULL, mx, d);
        if (lane == 0) s_b[0].mx[warp] = mx;
        if (warp == 0 && lane == 31) { s_b[0].nbM = aM[7]; s_b[0].nbI = 0.f; }
        // pre(1)
        float fc0 = fexit * (aLF + aU);
        float prevM = __shfl_up_sync(FULL, aM[7], 1);
        if (lane == 0) prevM = 0.f;
        float u = mscP0 * prevM;
        {
            float4 e0 = *(const float4*)(s_en + tid*4);
            float4 e1 = *(const float4*)(s_en + 256 + tid*4);
            float4 m0v = *(const float4*)(s_mtc + tid*4);
            float4 m1v = *(const float4*)(s_mtc + 256 + tid*4);
            float env[8] = {e0.x,e0.y,e0.z,e0.w,e1.x,e1.y,e1.z,e1.w};
            float mtv[8] = {m0v.x,m0v.y,m0v.z,m0v.w,m1v.x,m1v.y,m1v.z,m1v.w};
            pre[0] = fmaf(mtv[0], prevM, env[0]*fc0);
            #pragma unroll
            for (int k = 1; k < 8; k++) {
                pre[k] = fmaf(dtcP[k], u, fmaf(mtv[k], aM[k-1], env[k]*fc0));
                u += q[k-1];
            }
        }
        einsK = s_insd[s_seq[1]];
        {
            float4 mi0 = *(const float4*)(s_mic + tid*4);
            float4 mi1 = *(const float4*)(s_mic + 256 + tid*4);
            float miv[8] = {mi0.x,mi0.y,mi0.z,mi0.w,mi1.x,mi1.y,mi1.z,mi1.w};
            #pragma unroll
            for (int k = 0; k < 8; k++) aI[k] = einsK * miv[k] * aM[k];
        }
        c = s_seq[1];
        float4 ea = __ldg((const float4*)(g_em + c * 512 + m0));
        float4 eb = __ldg((const float4*)(g_em + c * 512 + m0 + 4));
        em[0]=ea.x; em[1]=ea.y; em[2]=ea.z; em[3]=ea.w;
        em[4]=eb.x; em[5]=eb.y; em[6]=eb.z; em[7]=eb.w;
        __syncthreads();
    }

    // ---- per-step body (compile-time flags; T runtime) ----
    auto step = [&](int T, bool MEAS, bool COMB, bool APPL, bool TAILF) {
        // head: scan
        float excl;
        {
            float x1 = __shfl_up_sync(FULL, x, 1);
            float x2 = __shfl_up_sync(FULL, x, 2);
            float x3 = __shfl_up_sync(FULL, x, 3);
            float s1 = fmaf(x3, c13, fmaf(x2, c12, fmaf(x1, c11, x)));
            x1 = __shfl_up_sync(FULL, s1, 4);
            x2 = __shfl_up_sync(FULL, s1, 8);
            x3 = __shfl_up_sync(FULL, s1, 12);
            float s2 = fmaf(x3, c23, fmaf(x2, c22, fmaf(x1, c21, s1)));
            x1 = __shfl_up_sync(FULL, s2, 16);
            excl = fmaf(x1, c31, s2);
        }
        if (warp == 0 && lane == 31)
            s_b[T & 1].wB0 = fmaf(excl, segA, iBown);
        __syncthreads();
        float nbMv, nbIv;
        {
            float pB = (warp == 1) ? s_b[T & 1].wB0 : 0.f;
            nbMv = s_b[(T - 1) & 1].nbM;
            nbIv = s_b[(T - 1) & 1].nbI;
            float base = fmaf(nbMv, Kown, pB);
            float v = fmaf(eAc, base, excl);
            #pragma unroll
            for (int k = 0; k < 8; k++)
                aM[k] = em[k] * fmaf(dtcP[k], v, pre[k]);
            if (warp == 1 && lane == 0)
                aM[0] = em[0] * fmaf(dtcP[0], pB,
                         fmaf(mt0, nbMv, fmaf(i20, nbIv, pre[0])));
        }
        if (TAILF) {
            int p = T & 1;
            #pragma unroll
            for (int j = 0; j < 7; j++) q[j] = aM[j] * mscP[j+1];
            float toty = ((q[0]+q[1]) + (q[2]+q[3])) + ((q[4]+q[5]) + q[6]);
            float y = cU * toty;
            float al1 = __shfl_up_sync(FULL, aM[7], 1);
            float y1  = __shfl_up_sync(FULL, y, 1);
            float a2  = __shfl_up_sync(FULL, aM[7], 2);
            iBown = fmaf(cUm, al1, y);
            x = (lane == 0) ? 0.f : fmaf(cUm1z, a2, y1);
            // mexit partial
            float mx;
            {
                float4 me0 = *(const float4*)(s_mec + tid*4);
                float4 me1 = *(const float4*)(s_mec + 256 + tid*4);
                mx = me0.x*aM[0]+me0.y*aM[1]+me0.z*aM[2]+me0.w*aM[3]
                   + me1.x*aM[4]+me1.y*aM[5]+me1.z*aM[6]+me1.w*aM[7];
            }
            #pragma unroll
            for (int d = 16; d; d >>= 1) mx += __shfl_xor_sync(FULL, mx, d);
            if (lane == 0) s_b[p].mx[warp] = mx;
            // flanks(T) using mexit(T-1)
            {
                float mexit = s_b[1-p].mx[0] + s_b[1-p].mx[1];
                float nLF = einsK * floop * aLF;
                float nU  = einsK * (fmaf(ep0, mexit, fbe0 * aLF) + (floop + fbe0) * aU);
                float nRF = einsK * (fmaf(ep1, mexit, fbe1 * (aLF + aU)) + floop * aRF);
                aLF = nLF; aU = nU; aRF = nRF;
            }
            float fcn = fexit * (aLF + aU);
            if (MEAS) {
                float tp = 0.f;
                #pragma unroll
                for (int k = 0; k < 8; k++) tp += aM[k] + aI[k];
                #pragma unroll
                for (int d = 16; d; d >>= 1) tp += __shfl_xor_sync(FULL, tp, d);
                if (lane == 0) s_b[p].tot[warp] = tp;
                flsave = aLF + aU + aRF;
            }
            if (COMB) {
                float sv = s_b[1-p].tot[0] + s_b[1-p].tot[1] + flsave + TINYF;
                invR = 1.f / sv;
                ll += logf(sv);
            }
            // pre(T+1)
            {
                float prevM = __shfl_up_sync(FULL, aM[7], 1);
                float prevI = __shfl_up_sync(FULL, aI[7], 1);
                if (lane == 0) { prevM = 0.f; prevI = 0.f; }
                float u = mscP0 * prevM;
                float4 e0 = *(const float4*)(s_en + tid*4);
                float4 e1 = *(const float4*)(s_en + 256 + tid*4);
                float4 m0v = *(const float4*)(s_mtc + tid*4);
                float4 m1v = *(const float4*)(s_mtc + 256 + tid*4);
                float4 i0v = *(const float4*)(s_i2mc + tid*4);
                float4 i1v = *(const float4*)(s_i2mc + 256 + tid*4);
                float env[8] = {e0.x,e0.y,e0.z,e0.w,e1.x,e1.y,e1.z,e1.w};
                float mtv[8] = {m0v.x,m0v.y,m0v.z,m0v.w,m1v.x,m1v.y,m1v.z,m1v.w};
                float i2v[8] = {i0v.x,i0v.y,i0v.z,i0v.w,i1v.x,i1v.y,i1v.z,i1v.w};
                pre[0] = fmaf(i2v[0], prevI, fmaf(mtv[0], prevM, env[0]*fcn));
                #pragma unroll
                for (int k = 1; k < 8; k++) {
                    pre[k] = fmaf(dtcP[k], u,
                             fmaf(i2v[k], aI[k-1],
                             fmaf(mtv[k], aM[k-1], env[k]*fcn)));
                    u += q[k-1];
                }
            }
            float eK1 = s_insd[s_seq[T + 1]];
            if (APPL) {
                #pragma unroll
                for (int k = 0; k < 8; k++) pre[k] *= invR;
                x *= invR; iBown *= invR; eK1 *= invR;
            }
            if (warp == 0 && lane == 31) {
                float sc = APPL ? invR : 1.f;
                s_b[p].nbM = aM[7] * sc;
                s_b[p].nbI = aI[7] * sc;
            }
            // aI(T+1)
            {
                float4 mi0 = *(const float4*)(s_mic + tid*4);
                float4 mi1 = *(const float4*)(s_mic + 256 + tid*4);
                float4 ii0 = *(const float4*)(s_iic + tid*4);
                float4 ii1 = *(const float4*)(s_iic + 256 + tid*4);
                float miv[8] = {mi0.x,mi0.y,mi0.z,mi0.w,mi1.x,mi1.y,mi1.z,mi1.w};
                float iiv[8] = {ii0.x,ii0.y,ii0.z,ii0.w,ii1.x,ii1.y,ii1.z,ii1.w};
                #pragma unroll
                for (int k = 0; k < 8; k++)
                    aI[k] = eK1 * fmaf(miv[k], aM[k], iiv[k] * aI[k]);
            }
            // em(T+1)
            {
                int cc = s_seq[T + 1];
                float4 ea = __ldg((const float4*)(g_em + cc * 512 + m0));
                float4 eb = __ldg((const float4*)(g_em + cc * 512 + m0 + 4));
                em[0]=ea.x; em[1]=ea.y; em[2]=ea.z; em[3]=ea.w;
                em[4]=eb.x; em[5]=eb.y; em[6]=eb.z; em[7]=eb.w;
            }
            einsK = eK1;
        }
    };

    // prologue: t = 1..8 (measure at 8)
    step(1, false, false, false, true);
    step(2, false, false, false, true);
    step(3, false, false, false, true);
    step(4, false, false, false, true);
    step(5, false, false, false, true);
    step(6, false, false, false, true);
    step(7, false, false, false, true);
    step(8, true,  false, false, true);
    // main: blocks of 8, t0 = 9..1009
    for (int t0 = 9; t0 <= 1009; t0 += 8) {
        step(t0+0, false, true,  false, true);   // t≡1: combine
        step(t0+1, false, false, false, true);
        step(t0+2, false, false, true,  true);   // t≡3: apply
        step(t0+3, false, false, false, true);
        step(t0+4, false, false, false, true);
        step(t0+5, false, false, false, true);
        step(t0+6, false, false, false, true);
        step(t0+7, true,  false, false, true);   // t≡0: measure
    }
    // epilogue: t = 1017..1023
    step(1017, false, true,  false, true);
    step(1018, false, false, false, true);
    step(1019, false, false, true,  true);
    step(1020, false, false, false, true);
    step(1021, false, false, false, true);
    step(1022, false, false, false, true);
    step(1023, false, false, false, false);   // head only

    // flanks(1023) using mexit(1022)
    {
        float mexit = s_b[0].mx[0] + s_b[0].mx[1];   // 1022 & 1 == 0
        float nLF = einsK * floop * aLF;
        float nU  = einsK * (fmaf(ep0, mexit, fbe0 * aLF) + (floop + fbe0) * aU);
        float nRF = einsK * (fmaf(ep1, mexit, fbe1 * (aLF + aU)) + floop * aRF);
        aLF = nLF; aU = nU; aRF = nRF;
    }
    // final mass -> log-likelihood
    {
        float tp = 0.f;
        #pragma unroll
        for (int k = 0; k < 8; k++) tp += aM[k] + aI[k];
        #pragma unroll
        for (int d = 16; d; d >>= 1) tp += __shfl_xor_sync(FULL, tp, d);
        __syncthreads();
        if (lane == 0) s_b[0].tot[warp] = tp;
        __syncthreads();
        float s = s_b[0].tot[0] + s_b[0].tot[1] + aLF + aU + aRF + TINYF;
        ll += logf(s);
        if (tid == 0) out[b] = ll;
    }
}

extern "C" void kernel_launch(void* const* d_in, const int* in_sizes, int n_in,
                              void* d_out, int out_size)
{
    setup_kernel<<<1, 512>>>(
        (const float*)d_in[1],  (const float*)d_in[2],  (const float*)d_in[3],
        (const float*)d_in[4],  (const float*)d_in[5],  (const float*)d_in[6],
        (const float*)d_in[7],  (const float*)d_in[8],  (const float*)d_in[9],
        (const float*)d_in[10], (const float*)d_in[11], (const float*)d_in[12],
        (const float*)d_in[13], (const float*)d_in[14], (const float*)d_in[15],
        (const float*)d_in[16], (const float*)d_in[17]);
    fwd_kernel<<<128, 64>>>((const int*)d_in[0], (float*)d_out);
}

// round 16
// speedup vs baseline: 1.7646x; 1.1053x over previous
#include <cuda_runtime.h>
#include <math.h>

#define TINYF 1.17549435e-38f

// ---------------- precomputed HMM parameters (device globals) ----------------
__device__ __align__(16) float g_em[25 * 512];   // transposed match emissions [sym][m]
__device__ float g_insd[32];                     // insert/flank emission dist
__device__ __align__(16) float g_enter[512];
__device__ __align__(16) float g_mtm[512];       // mtm_p[m-1]
__device__ __align__(16) float g_i2m[512];       // i2m_p[m-1]
__device__ __align__(16) float g_dtm[512];       // dtm_p[m-1]
__device__ __align__(16) float g_m2e[512];       // m2e_tot[m]
__device__ __align__(16) float g_m2i[512];       // m2i_p[m]
__device__ __align__(16) float g_i2i[512];       // i2i_p[m]
__device__ __align__(16) float g_asc[512];       // scan mult dtd_p[m-1] (a_0 = 1)
__device__ __align__(16) float g_msc[512];       // scan coeff mtd_p[m]
__device__ float g_scal[8];                      // floop,fexit,be,ep0,ep1,p0

// ---------------- setup: build all derived parameters (1 block, 512 thr) ----
__global__ void setup_kernel(
    const float* __restrict__ em_kernel, const float* __restrict__ ins_kernel,
    const float* __restrict__ flank_kernel, const float* __restrict__ btm,
    const float* __restrict__ m2e, const float* __restrict__ mtm,
    const float* __restrict__ m2i, const float* __restrict__ i2m,
    const float* __restrict__ i2i, const float* __restrict__ mtd,
    const float* __restrict__ dtm, const float* __restrict__ dtd,
    const float* __restrict__ lf_loop, const float* __restrict__ lf_exit,
    const float* __restrict__ e2u, const float* __restrict__ e2r,
    const float* __restrict__ e2t)
{
    __shared__ float red[512];
    __shared__ float incl[512];
    int m = threadIdx.x;

    float dtmp_m1 = 0.f, dtdp_m1 = 0.f;
    if (m >= 1) {
        float a = dtm[m-1], b = dtd[m-1], mx = fmaxf(a, b);
        float ea = expf(a-mx), eb = expf(b-mx), z = ea+eb;
        dtmp_m1 = ea/z; dtdp_m1 = eb/z;
    }
    float dtdp_m = 0.f;
    if (m <= 510) {
        float a = dtm[m], b = dtd[m], mx = fmaxf(a, b);
        float ea = expf(a-mx), eb = expf(b-mx);
        dtdp_m = eb/(ea+eb);
    }
    float m2ip_m = 0.f, m2ep_m = 0.f, mtdp_next = 0.f;
    if (m <= 510) {
        float v0 = mtm[m], v1 = m2i[m], v2 = m2e[m], v3 = mtd[m+1];
        float mx = fmaxf(fmaxf(v0,v1), fmaxf(v2,v3));
        float e0 = expf(v0-mx), e1 = expf(v1-mx), e2 = expf(v2-mx), e3 = expf(v3-mx);
        float z = e0+e1+e2+e3;
        m2ip_m = e1/z; m2ep_m = e2/z; mtdp_next = e3/z;
    }
    float mtmp_m1 = 0.f, mtdp_m_mid = 0.f;
    if (m >= 1) {
        float v0 = mtm[m-1], v1 = m2i[m-1], v2 = m2e[m-1], v3 = mtd[m];
        float mx = fmaxf(fmaxf(v0,v1), fmaxf(v2,v3));
        float e0 = expf(v0-mx), e1 = expf(v1-mx), e2 = expf(v2-mx), e3 = expf(v3-mx);
        float z = e0+e1+e2+e3;
        mtmp_m1 = e0/z; mtdp_m_mid = e3/z;
    }
    float i2ip_m = 0.f;
    if (m <= 510) {
        float a = i2m[m], b = i2i[m], mx = fmaxf(a, b);
        float ea = expf(a-mx), eb = expf(b-mx);
        i2ip_m = eb/(ea+eb);
    }
    float i2mp_m1 = 0.f;
    if (m >= 1) {
        float a = i2m[m-1], b = i2i[m-1], mx = fmaxf(a, b);
        float ea = expf(a-mx), eb = expf(b-mx);
        i2mp_m1 = ea/(ea+eb);
    }

    float bx = btm[m];
    red[m] = bx; __syncthreads();
    for (int s = 256; s > 0; s >>= 1) { if (m < s) red[m] = fmaxf(red[m], red[m+s]); __syncthreads(); }
    float bmx = fmaxf(red[0], mtd[0]);
    __syncthreads();
    float bex = expf(bx - bmx);
    red[m] = bex; __syncthreads();
    for (int s = 256; s > 0; s >>= 1) { if (m < s) red[m] += red[m+s]; __syncthreads(); }
    float bz = red[0] + expf(mtd[0] - bmx);
    __syncthreads();
    float btmp_m  = bex / bz;
    float mtd_p0  = expf(mtd[0] - bmx) / bz;

    incl[m] = (m <= 510) ? logf(dtdp_m) : 0.f;
    __syncthreads();
    for (int d = 1; d < 512; d <<= 1) {
        float v = incl[m];
        float add = (m >= d) ? incl[m-d] : 0.f;
        __syncthreads();
        incl[m] = v + add;
        __syncthreads();
    }
    float cp511 = incl[510];
    float cpm1  = (m >= 2) ? incl[m-2] : 0.f;
    float cpp1  = incl[m];
    float be = mtd_p0 * expf(cp511);
    float enter_m = btmp_m + ((m >= 1) ? mtd_p0 * expf(cpm1) * dtmp_m1 : 0.f);
    float m2etot = (m <= 510) ? (m2ep_m + mtdp_next * expf(cp511 - cpp1)) : 1.f;
    float mtdp_m = (m == 0) ? mtd_p0 : mtdp_m_mid;

    g_enter[m] = enter_m;
    g_mtm[m]   = mtmp_m1;
    g_i2m[m]   = i2mp_m1;
    g_dtm[m]   = (m >= 1) ? dtmp_m1 : 0.f;
    g_m2e[m]   = m2etot;
    g_m2i[m]   = m2ip_m;
    g_i2i[m]   = i2ip_m;
    g_asc[m]   = (m >= 1) ? dtdp_m1 : 1.f;
    g_msc[m]   = mtdp_m;

    {
        const float* row = em_kernel + m * 25;
        float mxr = row[0];
        for (int s = 1; s < 25; s++) mxr = fmaxf(mxr, row[s]);
        float z = 0.f;
        for (int s = 0; s < 25; s++) z += expf(row[s] - mxr);
        float invz = 1.f / z;
        for (int s = 0; s < 25; s++) g_em[s * 512 + m] = expf(row[s] - mxr) * invz;
    }
    if (m == 0) {
        float mxi = ins_kernel[0];
        for (int s = 1; s < 25; s++) mxi = fmaxf(mxi, ins_kernel[s]);
        float z = 0.f;
        for (int s = 0; s < 25; s++) z += expf(ins_kernel[s] - mxi);
        for (int s = 0; s < 25; s++) g_insd[s] = expf(ins_kernel[s] - mxi) / z;
        float a = lf_loop[0], b = lf_exit[0], mx = fmaxf(a, b);
        float ea = expf(a-mx), eb = expf(b-mx), z2 = ea+eb;
        float u = e2u[0], r = e2r[0], t = e2t[0];
        float mxe = fmaxf(fmaxf(u, r), t);
        float eu = expf(u-mxe), er = expf(r-mxe), et = expf(t-mxe);
        float ze = eu + er + et;
        g_scal[0] = ea/z2;
        g_scal[1] = eb/z2;
        g_scal[2] = be;
        g_scal[3] = eu/ze;
        g_scal[4] = er/ze;
        g_scal[5] = 1.f / (1.f + expf(-flank_kernel[0]));
    }
}

// transposed smem layout for 64 threads, 8 elems each
#define SMX(k, l) (((k) >> 2) * 256 + (l) * 4 + ((k) & 3))

struct Buf { float wB0; float nbM, nbI; float mx[2]; float tot[2]; };

// ---------------- forward kernel: 1 CTA per batch, 64 threads, 2 warps ------
__global__ __launch_bounds__(64, 1)
void fwd_kernel(const int* __restrict__ seq, float* __restrict__ out)
{
    __shared__ int   s_seq[1024];
    __shared__ float s_insd[32];
    __shared__ __align__(16) float s_en[512], s_mtc[512], s_i2mc[512];
    __shared__ __align__(16) float s_mec[512], s_mic[512], s_iic[512];
    __shared__ Buf   s_b[2];

    const int tid = threadIdx.x, lane = tid & 31, warp = tid >> 5;
    const int b = blockIdx.x;
    const int m0 = tid * 8;
    const unsigned FULL = 0xffffffffu;

    {
        const int4* sp = (const int4*)(seq + b * 1024);
        #pragma unroll
        for (int k = 0; k < 4; k++)
            ((int4*)s_seq)[tid + 64 * k] = sp[tid + 64 * k];
        if (tid < 25) s_insd[tid] = g_insd[tid];
        for (int idx = tid; idx < 512; idx += 64) {
            int kk = idx & 7, ln = idx >> 3;
            s_en  [SMX(kk, ln)] = g_enter[idx];
            s_mtc [SMX(kk, ln)] = g_mtm[idx];
            s_i2mc[SMX(kk, ln)] = g_i2m[idx];
            s_mec [SMX(kk, ln)] = g_m2e[idx];
            s_mic [SMX(kk, ln)] = g_m2i[idx];
            s_iic [SMX(kk, ln)] = g_i2i[idx];
        }
    }

    // hot per-thread constants
    float dtcP[8], mscP[8];
    float cU, cUm, segA, mscP0, mt0, i20;
    {
        float asc[8], msc[8], dtc[8];
        #pragma unroll
        for (int h = 0; h < 2; h++) {
            float4 v;
            v = *(const float4*)(g_asc + m0 + 4*h); asc[4*h]=v.x; asc[4*h+1]=v.y; asc[4*h+2]=v.z; asc[4*h+3]=v.w;
            v = *(const float4*)(g_msc + m0 + 4*h); msc[4*h]=v.x; msc[4*h+1]=v.y; msc[4*h+2]=v.z; msc[4*h+3]=v.w;
            v = *(const float4*)(g_dtm + m0 + 4*h); dtc[4*h]=v.x; dtc[4*h+1]=v.y; dtc[4*h+2]=v.z; dtc[4*h+3]=v.w;
        }
        float P[8];
        P[0] = asc[0];
        #pragma unroll
        for (int k = 1; k < 8; k++) P[k] = P[k-1] * asc[k];
        #pragma unroll
        for (int k = 0; k < 8; k++) mscP[k] = msc[k] / P[k];
        dtcP[0] = dtc[0];
        #pragma unroll
        for (int k = 1; k < 8; k++) dtcP[k] = dtc[k] * P[k-1];
        segA = P[7]; cU = P[7]; mscP0 = mscP[0];
        cUm = cU * mscP0;
        mt0 = g_mtm[m0]; i20 = g_i2m[m0];
    }

    const float floop = g_scal[0], fexit = g_scal[1], be = g_scal[2];
    const float ep0 = g_scal[3], ep1 = g_scal[4], p0 = g_scal[5];
    const float fbe0 = fexit * be * ep0, fbe1 = fexit * be * ep1;
    const float Kown = (warp == 1) ? (g_msc[256] / g_asc[256]) : 0.f;

    // window weights: W[d] = prod_{i=lane-d+1}^{lane-1} segA_i (0 if d > lane)
    float w1, w2, w3, w4, w5, w6, w7, w8;
    {
        w1 = (lane >= 1) ? 1.f : 0.f;
        float prod = 1.f;
        prod *= __shfl_up_sync(FULL, segA, 1); w2 = (lane >= 2) ? prod : 0.f;
        prod *= __shfl_up_sync(FULL, segA, 2); w3 = (lane >= 3) ? prod : 0.f;
        prod *= __shfl_up_sync(FULL, segA, 3); w4 = (lane >= 4) ? prod : 0.f;
        prod *= __shfl_up_sync(FULL, segA, 4); w5 = (lane >= 5) ? prod : 0.f;
        prod *= __shfl_up_sync(FULL, segA, 5); w6 = (lane >= 6) ? prod : 0.f;
        prod *= __shfl_up_sync(FULL, segA, 6); w7 = (lane >= 7) ? prod : 0.f;
        prod *= __shfl_up_sync(FULL, segA, 7); w8 = (lane >= 8) ? prod : 0.f;
    }
    // eAc: exact product of segA over lanes < me (Hillis-Steele on shifted segA;
    // all shfls unconditional — the divergent-shfl form deadlocked in R15)
    float eAc;
    {
        float As = __shfl_up_sync(FULL, segA, 1);
        if (lane == 0) As = 1.f;
        float acc = As;
        float p1  = __shfl_up_sync(FULL, acc, 1);  if (lane >= 1)  acc *= p1;
        float p2  = __shfl_up_sync(FULL, acc, 2);  if (lane >= 2)  acc *= p2;
        float p4  = __shfl_up_sync(FULL, acc, 4);  if (lane >= 4)  acc *= p4;
        float p8  = __shfl_up_sync(FULL, acc, 8);  if (lane >= 8)  acc *= p8;
        float p16 = __shfl_up_sync(FULL, acc, 16); if (lane >= 16) acc *= p16;
        eAc = acc;
        if (lane == 0) eAc = 1.f;
    }
    __syncthreads();

    // ---- t = 0 init ----
    float aM[8], aI[8], em[8], pre[8], q[7];
    int c = s_seq[0];
    float eins0 = s_insd[c];
    {
        float4 ea = __ldg((const float4*)(g_em + c * 512 + m0));
        float4 eb = __ldg((const float4*)(g_em + c * 512 + m0 + 4));
        em[0]=ea.x; em[1]=ea.y; em[2]=ea.z; em[3]=ea.w;
        em[4]=eb.x; em[5]=eb.y; em[6]=eb.z; em[7]=eb.w;
    }
    const float q0f = 1.f - p0;
    {
        float4 e0 = *(const float4*)(s_en + tid*4);
        float4 e1 = *(const float4*)(s_en + 256 + tid*4);
        float env[8] = {e0.x,e0.y,e0.z,e0.w,e1.x,e1.y,e1.z,e1.w};
        #pragma unroll
        for (int k = 0; k < 8; k++) { aM[k] = q0f * env[k] * em[k]; aI[k] = 0.f; }
    }
    float aLF = p0 * eins0, aU = q0f * be * ep0 * eins0, aRF = q0f * be * ep1 * eins0;
    float ll;
    {
        float tp = 0.f;
        #pragma unroll
        for (int k = 0; k < 8; k++) tp += aM[k];
        #pragma unroll
        for (int d = 16; d; d >>= 1) tp += __shfl_xor_sync(FULL, tp, d);
        if (lane == 0) s_b[0].tot[warp] = tp;
        __syncthreads();
        float s = s_b[0].tot[0] + s_b[0].tot[1] + aLF + aU + aRF + TINYF;
        float inv = 1.f / s; ll = logf(s);
        #pragma unroll
        for (int k = 0; k < 8; k++) aM[k] *= inv;
        aLF *= inv; aU *= inv; aRF *= inv;
        __syncthreads();
    }

    // ---- priming for t=1 ----
    float excl, einsK, invR = 1.f, flsave = 0.f;
    {
        float al1 = __shfl_up_sync(FULL, aM[7], 1);
        if (lane == 0) al1 = 0.f;
        #pragma unroll
        for (int j = 0; j < 7; j++) q[j] = aM[j] * mscP[j+1];
        float toty = ((q[0]+q[1]) + (q[2]+q[3])) + ((q[4]+q[5]) + q[6]);
        float y = cU * toty;
        float iB = fmaf(cUm, al1, y);
        // window
        float s1 = __shfl_up_sync(FULL, iB, 1);
        float s2 = __shfl_up_sync(FULL, iB, 2);
        float s3 = __shfl_up_sync(FULL, iB, 3);
        float s4 = __shfl_up_sync(FULL, iB, 4);
        float s5 = __shfl_up_sync(FULL, iB, 5);
        float s6 = __shfl_up_sync(FULL, iB, 6);
        float s7 = __shfl_up_sync(FULL, iB, 7);
        float s8 = __shfl_up_sync(FULL, iB, 8);
        float e12 = fmaf(s2, w2, s1 * w1);
        float e34 = fmaf(s4, w4, s3 * w3);
        float e56 = fmaf(s6, w6, s5 * w5);
        float e78 = fmaf(s8, w8, s7 * w7);
        excl = (e12 + e34) + (e56 + e78);
        if (warp == 0 && lane == 31) {
            s_b[1].wB0 = fmaf(excl, segA, iB);
            s_b[1].nbM = aM[7];
            s_b[1].nbI = 0.f;
        }
        // mx(0)
        float mx;
        {
            float4 me0 = *(const float4*)(s_mec + tid*4);
            float4 me1 = *(const float4*)(s_mec + 256 + tid*4);
            mx = me0.x*aM[0]+me0.y*aM[1]+me0.z*aM[2]+me0.w*aM[3]
               + me1.x*aM[4]+me1.y*aM[5]+me1.z*aM[6]+me1.w*aM[7];
        }
        #pragma unroll
        for (int d = 16; d; d >>= 1) mx += __shfl_xor_sync(FULL, mx, d);
        if (lane == 0) s_b[0].mx[warp] = mx;
        // pre(1)
        float fc0 = fexit * (aLF + aU);
        float prevM = al1;   // already zeroed at lane 0
        float u = mscP0 * prevM;
        {
            float4 e0 = *(const float4*)(s_en + tid*4);
            float4 e1 = *(const float4*)(s_en + 256 + tid*4);
            float4 m0v = *(const float4*)(s_mtc + tid*4);
            float4 m1v = *(const float4*)(s_mtc + 256 + tid*4);
            float env[8] = {e0.x,e0.y,e0.z,e0.w,e1.x,e1.y,e1.z,e1.w};
            float mtv[8] = {m0v.x,m0v.y,m0v.z,m0v.w,m1v.x,m1v.y,m1v.z,m1v.w};
            pre[0] = fmaf(mtv[0], prevM, env[0]*fc0);
            #pragma unroll
            for (int k = 1; k < 8; k++) {
                pre[k] = fmaf(dtcP[k], u, fmaf(mtv[k], aM[k-1], env[k]*fc0));
                u += q[k-1];
            }
        }
        einsK = s_insd[s_seq[1]];
        {
            float4 mi0 = *(const float4*)(s_mic + tid*4);
            float4 mi1 = *(const float4*)(s_mic + 256 + tid*4);
            float miv[8] = {mi0.x,mi0.y,mi0.z,mi0.w,mi1.x,mi1.y,mi1.z,mi1.w};
            #pragma unroll
            for (int k = 0; k < 8; k++) aI[k] = einsK * miv[k] * aM[k];
        }
        c = s_seq[1];
        float4 ea = __ldg((const float4*)(g_em + c * 512 + m0));
        float4 eb = __ldg((const float4*)(g_em + c * 512 + m0 + 4));
        em[0]=ea.x; em[1]=ea.y; em[2]=ea.z; em[3]=ea.w;
        em[4]=eb.x; em[5]=eb.y; em[6]=eb.z; em[7]=eb.w;
        __syncthreads();
    }

    // ---- per-step body (compile-time flags; T runtime) ----
    auto step = [&](int T, bool MEAS, bool COMB, bool APPL, bool TAILF) {
        const int p = T & 1;
        // ---- head: consume precomputed excl + smem handoff ----
        {
            float pB = (warp == 1) ? s_b[p].wB0 : 0.f;
            float nbMv = s_b[p].nbM;
            float nbIv = s_b[p].nbI;
            float base = fmaf(nbMv, Kown, pB);
            float v = fmaf(eAc, base, excl);
            #pragma unroll
            for (int k = 0; k < 8; k++)
                aM[k] = em[k] * fmaf(dtcP[k], v, pre[k]);
            if (warp == 1 && lane == 0)
                aM[0] = em[0] * fmaf(dtcP[0], pB,
                         fmaf(mt0, nbMv, fmaf(i20, nbIv, pre[0])));
        }
        if (TAILF) {
            float al1 = __shfl_up_sync(FULL, aM[7], 1);
            if (lane == 0) al1 = 0.f;
            #pragma unroll
            for (int j = 0; j < 7; j++) q[j] = aM[j] * mscP[j+1];
            float toty = ((q[0]+q[1]) + (q[2]+q[3])) + ((q[4]+q[5]) + q[6]);
            float y = cU * toty;
            float iB = fmaf(cUm, al1, y);
            // mexit partial
            float mx;
            {
                float4 me0 = *(const float4*)(s_mec + tid*4);
                float4 me1 = *(const float4*)(s_mec + 256 + tid*4);
                mx = me0.x*aM[0]+me0.y*aM[1]+me0.z*aM[2]+me0.w*aM[3]
                   + me1.x*aM[4]+me1.y*aM[5]+me1.z*aM[6]+me1.w*aM[7];
            }
            #pragma unroll
            for (int d = 16; d; d >>= 1) mx += __shfl_xor_sync(FULL, mx, d);
            if (lane == 0) s_b[p].mx[warp] = mx;
            // flanks(T) using mexit(T-1)
            {
                float mexit = s_b[1-p].mx[0] + s_b[1-p].mx[1];
                float nLF = einsK * floop * aLF;
                float nU  = einsK * (fmaf(ep0, mexit, fbe0 * aLF) + (floop + fbe0) * aU);
                float nRF = einsK * (fmaf(ep1, mexit, fbe1 * (aLF + aU)) + floop * aRF);
                aLF = nLF; aU = nU; aRF = nRF;
            }
            float fcn = fexit * (aLF + aU);
            if (MEAS) {
                float tp = 0.f;
                #pragma unroll
                for (int k = 0; k < 8; k++) tp += aM[k] + aI[k];
                #pragma unroll
                for (int d = 16; d; d >>= 1) tp += __shfl_xor_sync(FULL, tp, d);
                if (lane == 0) s_b[p].tot[warp] = tp;
                flsave = aLF + aU + aRF;
            }
            if (COMB) {
                float sv = s_b[1-p].tot[0] + s_b[1-p].tot[1] + flsave + TINYF;
                invR = 1.f / sv;
                ll += logf(sv);
            }
            // pre(T+1)
            {
                float prevM = al1;
                float prevI = __shfl_up_sync(FULL, aI[7], 1);
                if (lane == 0) prevI = 0.f;
                float u = mscP0 * prevM;
                float4 e0 = *(const float4*)(s_en + tid*4);
                float4 e1 = *(const float4*)(s_en + 256 + tid*4);
                float4 m0v = *(const float4*)(s_mtc + tid*4);
                float4 m1v = *(const float4*)(s_mtc + 256 + tid*4);
                float4 i0v = *(const float4*)(s_i2mc + tid*4);
                float4 i1v = *(const float4*)(s_i2mc + 256 + tid*4);
                float env[8] = {e0.x,e0.y,e0.z,e0.w,e1.x,e1.y,e1.z,e1.w};
                float mtv[8] = {m0v.x,m0v.y,m0v.z,m0v.w,m1v.x,m1v.y,m1v.z,m1v.w};
                float i2v[8] = {i0v.x,i0v.y,i0v.z,i0v.w,i1v.x,i1v.y,i1v.z,i1v.w};
                pre[0] = fmaf(i2v[0], prevI, fmaf(mtv[0], prevM, env[0]*fcn));
                #pragma unroll
                for (int k = 1; k < 8; k++) {
                    pre[k] = fmaf(dtcP[k], u,
                             fmaf(i2v[k], aI[k-1],
                             fmaf(mtv[k], aM[k-1], env[k]*fcn)));
                    u += q[k-1];
                }
            }
            float eK1 = s_insd[s_seq[T + 1]];
            if (APPL) {
                #pragma unroll
                for (int k = 0; k < 8; k++) pre[k] *= invR;
                iB *= invR; eK1 *= invR;
            }
            // window -> excl(T+1)
            {
                float s1 = __shfl_up_sync(FULL, iB, 1);
                float s2 = __shfl_up_sync(FULL, iB, 2);
                float s3 = __shfl_up_sync(FULL, iB, 3);
                float s4 = __shfl_up_sync(FULL, iB, 4);
                float s5 = __shfl_up_sync(FULL, iB, 5);
                float s6 = __shfl_up_sync(FULL, iB, 6);
                float s7 = __shfl_up_sync(FULL, iB, 7);
                float s8 = __shfl_up_sync(FULL, iB, 8);
                float e12 = fmaf(s2, w2, s1 * w1);
                float e34 = fmaf(s4, w4, s3 * w3);
                float e56 = fmaf(s6, w6, s5 * w5);
                float e78 = fmaf(s8, w8, s7 * w7);
                excl = (e12 + e34) + (e56 + e78);
            }
            if (warp == 0 && lane == 31) {
                float sc = APPL ? invR : 1.f;
                s_b[1-p].wB0 = fmaf(excl, segA, iB);
                s_b[1-p].nbM = aM[7] * sc;
                s_b[1-p].nbI = aI[7] * sc;
            }
            // aI(T+1)
            {
                float4 mi0 = *(const float4*)(s_mic + tid*4);
                float4 mi1 = *(const float4*)(s_mic + 256 + tid*4);
                float4 ii0 = *(const float4*)(s_iic + tid*4);
                float4 ii1 = *(const float4*)(s_iic + 256 + tid*4);
                float miv[8] = {mi0.x,mi0.y,mi0.z,mi0.w,mi1.x,mi1.y,mi1.z,mi1.w};
                float iiv[8] = {ii0.x,ii0.y,ii0.z,ii0.w,ii1.x,ii1.y,ii1.z,ii1.w};
                #pragma unroll
                for (int k = 0; k < 8; k++)
                    aI[k] = eK1 * fmaf(miv[k], aM[k], iiv[k] * aI[k]);
            }
            // em(T+1)
            {
                int cc = s_seq[T + 1];
                float4 ea = __ldg((const float4*)(g_em + cc * 512 + m0));
                float4 eb = __ldg((const float4*)(g_em + cc * 512 + m0 + 4));
                em[0]=ea.x; em[1]=ea.y; em[2]=ea.z; em[3]=ea.w;
                em[4]=eb.x; em[5]=eb.y; em[6]=eb.z; em[7]=eb.w;
            }
            einsK = eK1;
            __syncthreads();
        }
    };

    // prologue: t = 1..8 (measure at 8)
    step(1, false, false, false, true);
    step(2, false, false, false, true);
    step(3, false, false, false, true);
    step(4, false, false, false, true);
    step(5, false, false, false, true);
    step(6, false, false, false, true);
    step(7, false, false, false, true);
    step(8, true,  false, false, true);
    // main: blocks of 8, t0 = 9..1009
    for (int t0 = 9; t0 <= 1009; t0 += 8) {
        step(t0+0, false, true,  false, true);   // t≡1: combine
        step(t0+1, false, false, false, true);
        step(t0+2, false, false, true,  true);   // t≡3: apply
        step(t0+3, false, false, false, true);
        step(t0+4, false, false, false, true);
        step(t0+5, false, false, false, true);
        step(t0+6, false, false, false, true);
        step(t0+7, true,  false, false, true);   // t≡0: measure
    }
    // epilogue: t = 1017..1023
    step(1017, false, true,  false, true);
    step(1018, false, false, false, true);
    step(1019, false, false, true,  true);
    step(1020, false, false, false, true);
    step(1021, false, false, false, true);
    step(1022, false, false, false, true);
    step(1023, false, false, false, false);   // head only, no barrier

    // flanks(1023) using mexit(1022)
    {
        float mexit = s_b[0].mx[0] + s_b[0].mx[1];   // 1022 & 1 == 0
        float nLF = einsK * floop * aLF;
        float nU  = einsK * (fmaf(ep0, mexit, fbe0 * aLF) + (floop + fbe0) * aU);
        float nRF = einsK * (fmaf(ep1, mexit, fbe1 * (aLF + aU)) + floop * aRF);
        aLF = nLF; aU = nU; aRF = nRF;
    }
    // final mass -> log-likelihood
    {
        float tp = 0.f;
        #pragma unroll
        for (int k = 0; k < 8; k++) tp += aM[k] + aI[k];
        #pragma unroll
        for (int d = 16; d; d >>= 1) tp += __shfl_xor_sync(FULL, tp, d);
        __syncthreads();
        if (lane == 0) s_b[0].tot[warp] = tp;
        __syncthreads();
        float s = s_b[0].tot[0] + s_b[0].tot[1] + aLF + aU + aRF + TINYF;
        ll += logf(s);
        if (tid == 0) out[b] = ll;
    }
}

extern "C" void kernel_launch(void* const* d_in, const int* in_sizes, int n_in,
                              void* d_out, int out_size)
{
    setup_kernel<<<1, 512>>>(
        (const float*)d_in[1],  (const float*)d_in[2],  (const float*)d_in[3],
        (const float*)d_in[4],  (const float*)d_in[5],  (const float*)d_in[6],
        (const float*)d_in[7],  (const float*)d_in[8],  (const float*)d_in[9],
        (const float*)d_in[10], (const float*)d_in[11], (const float*)d_in[12],
        (const float*)d_in[13], (const float*)d_in[14], (const float*)d_in[15],
        (const float*)d_in[16], (const float*)d_in[17]);
    fwd_kernel<<<128, 64>>>((const int*)d_in[0], (float*)d_out);
}

// round 17
// speedup vs baseline: 1.8168x; 1.0295x over previous
#include <cuda_runtime.h>
#include <math.h>

#define TINYF 1.17549435e-38f

// ---------------- precomputed HMM parameters (device globals) ----------------
__device__ __align__(16) float g_em[25 * 512];   // transposed match emissions [sym][m]
__device__ float g_insd[32];                     // insert/flank emission dist
__device__ __align__(16) float g_enter[512];
__device__ __align__(16) float g_mtm[512];       // mtm_p[m-1]
__device__ __align__(16) float g_i2m[512];       // i2m_p[m-1]
__device__ __align__(16) float g_dtm[512];       // dtm_p[m-1]
__device__ __align__(16) float g_m2e[512];       // m2e_tot[m]
__device__ __align__(16) float g_m2i[512];       // m2i_p[m]
__device__ __align__(16) float g_i2i[512];       // i2i_p[m]
__device__ __align__(16) float g_asc[512];       // scan mult dtd_p[m-1] (a_0 = 1)
__device__ __align__(16) float g_msc[512];       // scan coeff mtd_p[m]
__device__ float g_scal[8];                      // floop,fexit,be,ep0,ep1,p0

// ---------------- setup: build all derived parameters (1 block, 512 thr) ----
__global__ void setup_kernel(
    const float* __restrict__ em_kernel, const float* __restrict__ ins_kernel,
    const float* __restrict__ flank_kernel, const float* __restrict__ btm,
    const float* __restrict__ m2e, const float* __restrict__ mtm,
    const float* __restrict__ m2i, const float* __restrict__ i2m,
    const float* __restrict__ i2i, const float* __restrict__ mtd,
    const float* __restrict__ dtm, const float* __restrict__ dtd,
    const float* __restrict__ lf_loop, const float* __restrict__ lf_exit,
    const float* __restrict__ e2u, const float* __restrict__ e2r,
    const float* __restrict__ e2t)
{
    __shared__ float red[512];
    __shared__ float incl[512];
    int m = threadIdx.x;

    float dtmp_m1 = 0.f, dtdp_m1 = 0.f;
    if (m >= 1) {
        float a = dtm[m-1], b = dtd[m-1], mx = fmaxf(a, b);
        float ea = expf(a-mx), eb = expf(b-mx), z = ea+eb;
        dtmp_m1 = ea/z; dtdp_m1 = eb/z;
    }
    float dtdp_m = 0.f;
    if (m <= 510) {
        float a = dtm[m], b = dtd[m], mx = fmaxf(a, b);
        float ea = expf(a-mx), eb = expf(b-mx);
        dtdp_m = eb/(ea+eb);
    }
    float m2ip_m = 0.f, m2ep_m = 0.f, mtdp_next = 0.f;
    if (m <= 510) {
        float v0 = mtm[m], v1 = m2i[m], v2 = m2e[m], v3 = mtd[m+1];
        float mx = fmaxf(fmaxf(v0,v1), fmaxf(v2,v3));
        float e0 = expf(v0-mx), e1 = expf(v1-mx), e2 = expf(v2-mx), e3 = expf(v3-mx);
        float z = e0+e1+e2+e3;
        m2ip_m = e1/z; m2ep_m = e2/z; mtdp_next = e3/z;
    }
    float mtmp_m1 = 0.f, mtdp_m_mid = 0.f;
    if (m >= 1) {
        float v0 = mtm[m-1], v1 = m2i[m-1], v2 = m2e[m-1], v3 = mtd[m];
        float mx = fmaxf(fmaxf(v0,v1), fmaxf(v2,v3));
        float e0 = expf(v0-mx), e1 = expf(v1-mx), e2 = expf(v2-mx), e3 = expf(v3-mx);
        float z = e0+e1+e2+e3;
        mtmp_m1 = e0/z; mtdp_m_mid = e3/z;
    }
    float i2ip_m = 0.f;
    if (m <= 510) {
        float a = i2m[m], b = i2i[m], mx = fmaxf(a, b);
        float ea = expf(a-mx), eb = expf(b-mx);
        i2ip_m = eb/(ea+eb);
    }
    float i2mp_m1 = 0.f;
    if (m >= 1) {
        float a = i2m[m-1], b = i2i[m-1], mx = fmaxf(a, b);
        float ea = expf(a-mx), eb = expf(b-mx);
        i2mp_m1 = ea/(ea+eb);
    }

    float bx = btm[m];
    red[m] = bx; __syncthreads();
    for (int s = 256; s > 0; s >>= 1) { if (m < s) red[m] = fmaxf(red[m], red[m+s]); __syncthreads(); }
    float bmx = fmaxf(red[0], mtd[0]);
    __syncthreads();
    float bex = expf(bx - bmx);
    red[m] = bex; __syncthreads();
    for (int s = 256; s > 0; s >>= 1) { if (m < s) red[m] += red[m+s]; __syncthreads(); }
    float bz = red[0] + expf(mtd[0] - bmx);
    __syncthreads();
    float btmp_m  = bex / bz;
    float mtd_p0  = expf(mtd[0] - bmx) / bz;

    incl[m] = (m <= 510) ? logf(dtdp_m) : 0.f;
    __syncthreads();
    for (int d = 1; d < 512; d <<= 1) {
        float v = incl[m];
        float add = (m >= d) ? incl[m-d] : 0.f;
        __syncthreads();
        incl[m] = v + add;
        __syncthreads();
    }
    float cp511 = incl[510];
    float cpm1  = (m >= 2) ? incl[m-2] : 0.f;
    float cpp1  = incl[m];
    float be = mtd_p0 * expf(cp511);
    float enter_m = btmp_m + ((m >= 1) ? mtd_p0 * expf(cpm1) * dtmp_m1 : 0.f);
    float m2etot = (m <= 510) ? (m2ep_m + mtdp_next * expf(cp511 - cpp1)) : 1.f;
    float mtdp_m = (m == 0) ? mtd_p0 : mtdp_m_mid;

    g_enter[m] = enter_m;
    g_mtm[m]   = mtmp_m1;
    g_i2m[m]   = i2mp_m1;
    g_dtm[m]   = (m >= 1) ? dtmp_m1 : 0.f;
    g_m2e[m]   = m2etot;
    g_m2i[m]   = m2ip_m;
    g_i2i[m]   = i2ip_m;
    g_asc[m]   = (m >= 1) ? dtdp_m1 : 1.f;
    g_msc[m]   = mtdp_m;

    {
        const float* row = em_kernel + m * 25;
        float mxr = row[0];
        for (int s = 1; s < 25; s++) mxr = fmaxf(mxr, row[s]);
        float z = 0.f;
        for (int s = 0; s < 25; s++) z += expf(row[s] - mxr);
        float invz = 1.f / z;
        for (int s = 0; s < 25; s++) g_em[s * 512 + m] = expf(row[s] - mxr) * invz;
    }
    if (m == 0) {
        float mxi = ins_kernel[0];
        for (int s = 1; s < 25; s++) mxi = fmaxf(mxi, ins_kernel[s]);
        float z = 0.f;
        for (int s = 0; s < 25; s++) z += expf(ins_kernel[s] - mxi);
        for (int s = 0; s < 25; s++) g_insd[s] = expf(ins_kernel[s] - mxi) / z;
        float a = lf_loop[0], b = lf_exit[0], mx = fmaxf(a, b);
        float ea = expf(a-mx), eb = expf(b-mx), z2 = ea+eb;
        float u = e2u[0], r = e2r[0], t = e2t[0];
        float mxe = fmaxf(fmaxf(u, r), t);
        float eu = expf(u-mxe), er = expf(r-mxe), et = expf(t-mxe);
        float ze = eu + er + et;
        g_scal[0] = ea/z2;
        g_scal[1] = eb/z2;
        g_scal[2] = be;
        g_scal[3] = eu/ze;
        g_scal[4] = er/ze;
        g_scal[5] = 1.f / (1.f + expf(-flank_kernel[0]));
    }
}

struct Buf { float E[4]; float nbM[4], nbI[4]; float mx[4]; float tot[4]; };

// ---------------- forward kernel: 1 CTA per batch, 128 threads, 4 warps -----
// Each thread owns 4 states. Cross-warp coupling truncated: a whole warp's
// A-product is segA^32 ~ 1e-30 (fp32 zero), so each warp posts its segment
// total independently; consumers read only the immediate predecessor's slot.
__global__ __launch_bounds__(128, 1)
void fwd_kernel(const int* __restrict__ seq, float* __restrict__ out)
{
    __shared__ int   s_seq[1024];
    __shared__ float s_insd[32];
    __shared__ __align__(16) float s_en[512], s_mtc[512], s_i2mc[512];
    __shared__ __align__(16) float s_mec[512], s_mic[512], s_iic[512];
    __shared__ Buf   s_b[2];

    const int tid = threadIdx.x, lane = tid & 31, warp = tid >> 5;
    const int b = blockIdx.x;
    const int m0 = tid * 4;
    const unsigned FULL = 0xffffffffu;

    {
        const int4* sp = (const int4*)(seq + b * 1024);
        ((int4*)s_seq)[tid]       = sp[tid];
        ((int4*)s_seq)[tid + 128] = sp[tid + 128];
        if (tid < 25) s_insd[tid] = g_insd[tid];
        ((float4*)s_en)  [tid] = ((const float4*)g_enter)[tid];
        ((float4*)s_mtc) [tid] = ((const float4*)g_mtm)[tid];
        ((float4*)s_i2mc)[tid] = ((const float4*)g_i2m)[tid];
        ((float4*)s_mec) [tid] = ((const float4*)g_m2e)[tid];
        ((float4*)s_mic) [tid] = ((const float4*)g_m2i)[tid];
        ((float4*)s_iic) [tid] = ((const float4*)g_i2i)[tid];
    }

    // hot per-thread constants (4 states)
    float dtcP[4], mscP[4];
    float cU, cUm, segA, mscP0, mt0, i20;
    {
        float4 va = ((const float4*)g_asc)[tid];
        float4 vm = ((const float4*)g_msc)[tid];
        float4 vd = ((const float4*)g_dtm)[tid];
        float asc[4] = {va.x, va.y, va.z, va.w};
        float msc[4] = {vm.x, vm.y, vm.z, vm.w};
        float dtc[4] = {vd.x, vd.y, vd.z, vd.w};
        float P[4];
        P[0] = asc[0];
        #pragma unroll
        for (int k = 1; k < 4; k++) P[k] = P[k-1] * asc[k];
        #pragma unroll
        for (int k = 0; k < 4; k++) mscP[k] = msc[k] / P[k];
        dtcP[0] = dtc[0];
        #pragma unroll
        for (int k = 1; k < 4; k++) dtcP[k] = dtc[k] * P[k-1];
        segA = P[3]; cU = P[3]; mscP0 = mscP[0];
        cUm = cU * mscP0;
        mt0 = g_mtm[m0]; i20 = g_i2m[m0];
    }

    const float floop = g_scal[0], fexit = g_scal[1], be = g_scal[2];
    const float ep0 = g_scal[3], ep1 = g_scal[4], p0 = g_scal[5];
    const float fbe0 = fexit * be * ep0, fbe1 = fexit * be * ep1;
    const float Kown = (warp > 0) ? (g_msc[warp * 128] / g_asc[warp * 128]) : 0.f;

    // window weights: w[d-1] multiplies iB(lane-d), d = 1..10
    float w[10];
    {
        w[0] = (lane >= 1) ? 1.f : 0.f;
        float prod = 1.f;
        #pragma unroll
        for (int d = 1; d < 10; d++) {
            prod *= __shfl_up_sync(FULL, segA, d);
            w[d] = (lane >= d + 1) ? prod : 0.f;
        }
    }
    // eAc: exact product of segA over lanes < me (all shfls unconditional)
    float eAc;
    {
        float As = __shfl_up_sync(FULL, segA, 1);
        if (lane == 0) As = 1.f;
        float acc = As;
        float p1  = __shfl_up_sync(FULL, acc, 1);  if (lane >= 1)  acc *= p1;
        float p2  = __shfl_up_sync(FULL, acc, 2);  if (lane >= 2)  acc *= p2;
        float p4  = __shfl_up_sync(FULL, acc, 4);  if (lane >= 4)  acc *= p4;
        float p8  = __shfl_up_sync(FULL, acc, 8);  if (lane >= 8)  acc *= p8;
        float p16 = __shfl_up_sync(FULL, acc, 16); if (lane >= 16) acc *= p16;
        eAc = acc;
        if (lane == 0) eAc = 1.f;
    }
    __syncthreads();

    // ---- t = 0 init ----
    float aM[4], aI[4], em[4], pre[4], q[3];
    int c = s_seq[0];
    float eins0 = s_insd[c];
    {
        float4 ev = __ldg((const float4*)(g_em + c * 512 + m0));
        em[0]=ev.x; em[1]=ev.y; em[2]=ev.z; em[3]=ev.w;
    }
    const float q0f = 1.f - p0;
    {
        float4 e0 = ((const float4*)s_en)[tid];
        float env[4] = {e0.x, e0.y, e0.z, e0.w};
        #pragma unroll
        for (int k = 0; k < 4; k++) { aM[k] = q0f * env[k] * em[k]; aI[k] = 0.f; }
    }
    float aLF = p0 * eins0, aU = q0f * be * ep0 * eins0, aRF = q0f * be * ep1 * eins0;
    float ll;
    {
        float tp = aM[0] + aM[1] + aM[2] + aM[3];
        #pragma unroll
        for (int d = 16; d; d >>= 1) tp += __shfl_xor_sync(FULL, tp, d);
        if (lane == 0) s_b[0].tot[warp] = tp;
        __syncthreads();
        float s = ((s_b[0].tot[0] + s_b[0].tot[1]) + (s_b[0].tot[2] + s_b[0].tot[3]))
                + aLF + aU + aRF + TINYF;
        float inv = 1.f / s; ll = logf(s);
        #pragma unroll
        for (int k = 0; k < 4; k++) aM[k] *= inv;
        aLF *= inv; aU *= inv; aRF *= inv;
        __syncthreads();
    }

    // ---- priming for t=1 ----
    float excl, einsK, invR = 1.f, flsave = 0.f;
    {
        float al1 = __shfl_up_sync(FULL, aM[3], 1);
        if (lane == 0) al1 = 0.f;
        q[0] = aM[0] * mscP[1]; q[1] = aM[1] * mscP[2]; q[2] = aM[2] * mscP[3];
        float toty = (q[0] + q[1]) + q[2];
        float iB = fmaf(cUm, al1, cU * toty);
        // 10-term window
        {
            float s1 = __shfl_up_sync(FULL, iB, 1);
            float s2 = __shfl_up_sync(FULL, iB, 2);
            float s3 = __shfl_up_sync(FULL, iB, 3);
            float s4 = __shfl_up_sync(FULL, iB, 4);
            float s5 = __shfl_up_sync(FULL, iB, 5);
            float s6 = __shfl_up_sync(FULL, iB, 6);
            float s7 = __shfl_up_sync(FULL, iB, 7);
            float s8 = __shfl_up_sync(FULL, iB, 8);
            float s9 = __shfl_up_sync(FULL, iB, 9);
            float sA = __shfl_up_sync(FULL, iB, 10);
            float e1 = fmaf(s2, w[1], s1 * w[0]);
            float e2 = fmaf(s4, w[3], s3 * w[2]);
            float e3 = fmaf(s6, w[5], s5 * w[4]);
            float e4 = fmaf(s8, w[7], s7 * w[6]);
            float e5 = fmaf(sA, w[9], s9 * w[8]);
            excl = ((e1 + e2) + (e3 + e4)) + e5;
        }
        if (lane == 31) {
            s_b[1].E[warp]   = fmaf(excl, segA, iB);
            s_b[1].nbM[warp] = aM[3];
            s_b[1].nbI[warp] = 0.f;
        }
        // mx(0)
        float mx;
        {
            float4 me = ((const float4*)s_mec)[tid];
            mx = me.x*aM[0] + me.y*aM[1] + me.z*aM[2] + me.w*aM[3];
        }
        #pragma unroll
        for (int d = 16; d; d >>= 1) mx += __shfl_xor_sync(FULL, mx, d);
        if (lane == 0) s_b[0].mx[warp] = mx;
        // pre(1)
        float fc0 = fexit * (aLF + aU);
        float prevM = al1;
        float u = mscP0 * prevM;
        {
            float4 e0 = ((const float4*)s_en)[tid];
            float4 mv = ((const float4*)s_mtc)[tid];
            float env[4] = {e0.x, e0.y, e0.z, e0.w};
            float mtv[4] = {mv.x, mv.y, mv.z, mv.w};
            pre[0] = fmaf(mtv[0], prevM, env[0] * fc0);
            #pragma unroll
            for (int k = 1; k < 4; k++) {
                pre[k] = fmaf(dtcP[k], u, fmaf(mtv[k], aM[k-1], env[k] * fc0));
                u += q[k-1];
            }
        }
        einsK = s_insd[s_seq[1]];
        {
            float4 mi = ((const float4*)s_mic)[tid];
            float miv[4] = {mi.x, mi.y, mi.z, mi.w};
            #pragma unroll
            for (int k = 0; k < 4; k++) aI[k] = einsK * miv[k] * aM[k];
        }
        c = s_seq[1];
        float4 ev = __ldg((const float4*)(g_em + c * 512 + m0));
        em[0]=ev.x; em[1]=ev.y; em[2]=ev.z; em[3]=ev.w;
        __syncthreads();
    }

    // ---- per-step body (compile-time flags; T runtime) ----
    auto step = [&](int T, bool MEAS, bool COMB, bool APPL, bool TAILF) {
        const int p = T & 1;
        // ---- head ----
        {
            float pB   = (warp > 0) ? s_b[p].E[warp - 1]   : 0.f;
            float nbMv = (warp > 0) ? s_b[p].nbM[warp - 1] : 0.f;
            float nbIv = (warp > 0) ? s_b[p].nbI[warp - 1] : 0.f;
            float base = fmaf(nbMv, Kown, pB);
            float v = fmaf(eAc, base, excl);
            #pragma unroll
            for (int k = 0; k < 4; k++)
                aM[k] = em[k] * fmaf(dtcP[k], v, pre[k]);
            if (warp > 0 && lane == 0)
                aM[0] = em[0] * fmaf(dtcP[0], pB,
                         fmaf(mt0, nbMv, fmaf(i20, nbIv, pre[0])));
        }
        if (TAILF) {
            float al1 = __shfl_up_sync(FULL, aM[3], 1);
            if (lane == 0) al1 = 0.f;
            q[0] = aM[0] * mscP[1]; q[1] = aM[1] * mscP[2]; q[2] = aM[2] * mscP[3];
            float toty = (q[0] + q[1]) + q[2];
            float iB = fmaf(cUm, al1, cU * toty);
            // mexit partial
            float mx;
            {
                float4 me = ((const float4*)s_mec)[tid];
                mx = me.x*aM[0] + me.y*aM[1] + me.z*aM[2] + me.w*aM[3];
            }
            #pragma unroll
            for (int d = 16; d; d >>= 1) mx += __shfl_xor_sync(FULL, mx, d);
            if (lane == 0) s_b[p].mx[warp] = mx;
            // flanks(T) using mexit(T-1)
            {
                float mexit = (s_b[1-p].mx[0] + s_b[1-p].mx[1])
                            + (s_b[1-p].mx[2] + s_b[1-p].mx[3]);
                float nLF = einsK * floop * aLF;
                float nU  = einsK * (fmaf(ep0, mexit, fbe0 * aLF) + (floop + fbe0) * aU);
                float nRF = einsK * (fmaf(ep1, mexit, fbe1 * (aLF + aU)) + floop * aRF);
                aLF = nLF; aU = nU; aRF = nRF;
            }
            float fcn = fexit * (aLF + aU);
            if (MEAS) {
                float tp = (aM[0] + aM[1]) + (aM[2] + aM[3])
                         + (aI[0] + aI[1]) + (aI[2] + aI[3]);
                #pragma unroll
                for (int d = 16; d; d >>= 1) tp += __shfl_xor_sync(FULL, tp, d);
                if (lane == 0) s_b[p].tot[warp] = tp;
                flsave = aLF + aU + aRF;
            }
            if (COMB) {
                float sv = ((s_b[1-p].tot[0] + s_b[1-p].tot[1])
                          + (s_b[1-p].tot[2] + s_b[1-p].tot[3])) + flsave + TINYF;
                invR = 1.f / sv;
                ll += logf(sv);
            }
            // pre(T+1)
            {
                float prevM = al1;
                float prevI = __shfl_up_sync(FULL, aI[3], 1);
                if (lane == 0) prevI = 0.f;
                float u = mscP0 * prevM;
                float4 e0 = ((const float4*)s_en)[tid];
                float4 mv = ((const float4*)s_mtc)[tid];
                float4 iv = ((const float4*)s_i2mc)[tid];
                float env[4] = {e0.x, e0.y, e0.z, e0.w};
                float mtv[4] = {mv.x, mv.y, mv.z, mv.w};
                float i2v[4] = {iv.x, iv.y, iv.z, iv.w};
                pre[0] = fmaf(i2v[0], prevI, fmaf(mtv[0], prevM, env[0] * fcn));
                #pragma unroll
                for (int k = 1; k < 4; k++) {
                    pre[k] = fmaf(dtcP[k], u,
                             fmaf(i2v[k], aI[k-1],
                             fmaf(mtv[k], aM[k-1], env[k] * fcn)));
                    u += q[k-1];
                }
            }
            float eK1 = s_insd[s_seq[T + 1]];
            if (APPL) {
                #pragma unroll
                for (int k = 0; k < 4; k++) pre[k] *= invR;
                iB *= invR; eK1 *= invR;
            }
            // window -> excl(T+1)
            {
                float s1 = __shfl_up_sync(FULL, iB, 1);
                float s2 = __shfl_up_sync(FULL, iB, 2);
                float s3 = __shfl_up_sync(FULL, iB, 3);
                float s4 = __shfl_up_sync(FULL, iB, 4);
                float s5 = __shfl_up_sync(FULL, iB, 5);
                float s6 = __shfl_up_sync(FULL, iB, 6);
                float s7 = __shfl_up_sync(FULL, iB, 7);
                float s8 = __shfl_up_sync(FULL, iB, 8);
                float s9 = __shfl_up_sync(FULL, iB, 9);
                float sA = __shfl_up_sync(FULL, iB, 10);
                float e1 = fmaf(s2, w[1], s1 * w[0]);
                float e2 = fmaf(s4, w[3], s3 * w[2]);
                float e3 = fmaf(s6, w[5], s5 * w[4]);
                float e4 = fmaf(s8, w[7], s7 * w[6]);
                float e5 = fmaf(sA, w[9], s9 * w[8]);
                excl = ((e1 + e2) + (e3 + e4)) + e5;
            }
            if (lane == 31) {
                float sc = APPL ? invR : 1.f;
                s_b[1-p].E[warp]   = fmaf(excl, segA, iB);
                s_b[1-p].nbM[warp] = aM[3] * sc;
                s_b[1-p].nbI[warp] = aI[3] * sc;
            }
            // aI(T+1)
            {
                float4 mi = ((const float4*)s_mic)[tid];
                float4 ii = ((const float4*)s_iic)[tid];
                float miv[4] = {mi.x, mi.y, mi.z, mi.w};
                float iiv[4] = {ii.x, ii.y, ii.z, ii.w};
                #pragma unroll
                for (int k = 0; k < 4; k++)
                    aI[k] = eK1 * fmaf(miv[k], aM[k], iiv[k] * aI[k]);
            }
            // em(T+1)
            {
                int cc = s_seq[T + 1];
                float4 ev = __ldg((const float4*)(g_em + cc * 512 + m0));
                em[0]=ev.x; em[1]=ev.y; em[2]=ev.z; em[3]=ev.w;
            }
            einsK = eK1;
            __syncthreads();
        }
    };

    // prologue: t = 1..8 (measure at 8)
    step(1, false, false, false, true);
    step(2, false, false, false, true);
    step(3, false, false, false, true);
    step(4, false, false, false, true);
    step(5, false, false, false, true);
    step(6, false, false, false, true);
    step(7, false, false, false, true);
    step(8, true,  false, false, true);
    // main: blocks of 8, t0 = 9..1009
    for (int t0 = 9; t0 <= 1009; t0 += 8) {
        step(t0+0, false, true,  false, true);   // t≡1: combine
        step(t0+1, false, false, false, true);
        step(t0+2, false, false, true,  true);   // t≡3: apply
        step(t0+3, false, false, false, true);
        step(t0+4, false, false, false, true);
        step(t0+5, false, false, false, true);
        step(t0+6, false, false, false, true);
        step(t0+7, true,  false, false, true);   // t≡0: measure
    }
    // epilogue: t = 1017..1023
    step(1017, false, true,  false, true);
    step(1018, false, false, false, true);
    step(1019, false, false, true,  true);
    step(1020, false, false, false, true);
    step(1021, false, false, false, true);
    step(1022, false, false, false, true);
    step(1023, false, false, false, false);   // head only, no barrier

    // flanks(1023) using mexit(1022)
    {
        float mexit = (s_b[0].mx[0] + s_b[0].mx[1]) + (s_b[0].mx[2] + s_b[0].mx[3]);
        float nLF = einsK * floop * aLF;
        float nU  = einsK * (fmaf(ep0, mexit, fbe0 * aLF) + (floop + fbe0) * aU);
        float nRF = einsK * (fmaf(ep1, mexit, fbe1 * (aLF + aU)) + floop * aRF);
        aLF = nLF; aU = nU; aRF = nRF;
    }
    // final mass -> log-likelihood
    {
        float tp = (aM[0] + aM[1]) + (aM[2] + aM[3])
                 + (aI[0] + aI[1]) + (aI[2] + aI[3]);
        #pragma unroll
        for (int d = 16; d; d >>= 1) tp += __shfl_xor_sync(FULL, tp, d);
        __syncthreads();
        if (lane == 0) s_b[0].tot[warp] = tp;
        __syncthreads();
        float s = ((s_b[0].tot[0] + s_b[0].tot[1]) + (s_b[0].tot[2] + s_b[0].tot[3]))
                + aLF + aU + aRF + TINYF;
        ll += logf(s);
        if (tid == 0) out[b] = ll;
    }
}

extern "C" void kernel_launch(void* const* d_in, const int* in_sizes, int n_in,
                              void* d_out, int out_size)
{
    setup_kernel<<<1, 512>>>(
        (const float*)d_in[1],  (const float*)d_in[2],  (const float*)d_in[3],
        (const float*)d_in[4],  (const float*)d_in[5],  (const float*)d_in[6],
        (const float*)d_in[7],  (const float*)d_in[8],  (const float*)d_in[9],
        (const float*)d_in[10], (const float*)d_in[11], (const float*)d_in[12],
        (const float*)d_in[13], (const float*)d_in[14], (const float*)d_in[15],
        (const float*)d_in[16], (const float*)d_in[17]);
    fwd_kernel<<<128, 128>>>((const int*)d_in[0], (float*)d_out);
}